// round 2
// baseline (speedup 1.0000x reference)
#include <cuda_runtime.h>
#include <math.h>

#define B  4096
#define T  50
#define U  128
#define N3 384
#define BT (B*T)
#define BN_EPS 1e-3f
#define LEAKY  3e-4f

// ------------ scratch (device globals; no allocation allowed) ------------
__device__ float g_Xp[BT*N3];        // GRU input projection   (300 MB)
__device__ float g_hs[BT*U];         // GRU hidden states      (100 MB)
__device__ float g_X3[BT*N3];        // AUGRU input projections(300 MB)
__device__ float g_ats[BT];          // attention scores
__device__ float g_hfin[B*U];        // AUGRU final state
__device__ float g_newsterm[B*U];    // news@(W1B+W1C)+b1
__device__ float g_Wau[U*N3];        // packed input  [Wu|Wr|Wc]
__device__ float g_Uau[U*N3];        // packed recur  [Uu|Ur|Uc]
__device__ float g_bau[N3];          // packed [bu|br|bc]
__device__ float g_W1x[U*U];         // W1A - W1B
__device__ float g_W1bc[U*U];        // W1B + W1C

__device__ __forceinline__ float sigf(float x){ return 1.f/(1.f+expf(-x)); }

// ------------------------------- prep -------------------------------
__global__ void prep_kernel(const float* __restrict__ Wu, const float* __restrict__ bu,
                            const float* __restrict__ Wr, const float* __restrict__ br,
                            const float* __restrict__ Wc, const float* __restrict__ bc,
                            const float* __restrict__ Uu, const float* __restrict__ Ur,
                            const float* __restrict__ Uc,
                            const float* __restrict__ attW1) {
  int id = blockIdx.x*blockDim.x + threadIdx.x;
  if (id < U*N3) {
    int k = id / N3, c = id % N3;
    float w, u;
    if (c < 128)      { w = Wu[k*128 + c];       u = Uu[k*128 + c]; }
    else if (c < 256) { w = Wr[k*128 + (c-128)]; u = Ur[k*128 + (c-128)]; }
    else              { w = Wc[k*128 + (c-256)]; u = Uc[k*128 + (c-256)]; }
    g_Wau[id] = w;
    g_Uau[id] = u;
  }
  if (id < N3)
    g_bau[id] = (id < 128) ? bu[id] : (id < 256 ? br[id-128] : bc[id-256]);
  if (id < U*U) {
    g_W1x[id]  = attW1[id]        - attW1[U*U + id];
    g_W1bc[id] = attW1[U*U + id]  + attW1[2*U*U + id];
  }
}

// ------------------------- generic GEMM, K=128 -------------------------
// C[m, 0..N) = A_row(m) @ W(128 x N) + bias,  N = gridDim.y*128, M = gridDim.x*64
// A row m lives at A + (m/P)*GS + (m%P)*128   (handles the T+1 stride of `inputs`)
__global__ void gemm_k128(const float* __restrict__ A, int P, long long GS,
                          const float* __restrict__ W, const float* __restrict__ bias,
                          float* __restrict__ C) {
  extern __shared__ float sm[];
  float* As = sm;               // 64 x 132 (padded)
  float* Bs = sm + 64*132;      // 128 x 128
  const int N  = gridDim.y * 128;
  const int m0 = blockIdx.x * 64;
  const int c0 = blockIdx.y * 128;
  const int tid = threadIdx.x;          // 256
  const int kq = tid >> 5, cq = tid & 31;
  #pragma unroll
  for (int it = 0; it < 16; ++it) {
    int k = kq + 8*it;
    float4 v = *(const float4*)(W + (long long)k*N + c0 + 4*cq);
    *(float4*)(Bs + k*128 + 4*cq) = v;
  }
  #pragma unroll
  for (int it = 0; it < 8; ++it) {
    int r = kq + 8*it;
    int m = m0 + r;
    const float* ap = A + (long long)(m/P)*GS + (long long)(m%P)*128;
    float4 v = *(const float4*)(ap + 4*cq);
    *(float4*)(As + r*132 + 4*cq) = v;
  }
  __syncthreads();
  const int tx = tid & 15, ty = tid >> 4;
  float acc[4][8];
  #pragma unroll
  for (int i=0;i<4;i++)
    #pragma unroll
    for (int j=0;j<8;j++) acc[i][j] = 0.f;
  #pragma unroll 2
  for (int k = 0; k < 128; k += 4) {
    float4 a[4];
    #pragma unroll
    for (int i=0;i<4;i++) a[i] = *(const float4*)(As + (ty*4+i)*132 + k);
    #pragma unroll
    for (int kk=0; kk<4; ++kk) {
      float bb[8];
      #pragma unroll
      for (int j=0;j<8;j++) bb[j] = Bs[(k+kk)*128 + tx + 16*j];
      #pragma unroll
      for (int i=0;i<4;i++) {
        float av = (&a[i].x)[kk];
        #pragma unroll
        for (int j=0;j<8;j++) acc[i][j] = fmaf(av, bb[j], acc[i][j]);
      }
    }
  }
  #pragma unroll
  for (int i=0;i<4;i++) {
    int m = m0 + ty*4 + i;
    #pragma unroll
    for (int j=0;j<8;j++) {
      int c = c0 + tx + 16*j;
      C[(long long)m*N + c] = acc[i][j] + bias[c];
    }
  }
}

// ------------------------------ GRU scan ------------------------------
// 16 batch rows per CTA, recurrent weight (128x384) in SMEM, 50 sequential steps.
__global__ void gru_scan_kernel(const float* __restrict__ Xp, const float* __restrict__ Ugru,
                                const float* __restrict__ b1, float* __restrict__ hs) {
  extern __shared__ float sm[];
  float* U_s = sm;            // 128*384
  float* h_s = sm + 128*384;  // 16*128
  float* b_s = h_s + 16*128;  // 384
  const int tid = threadIdx.x;      // 256
  const int b0 = blockIdx.x * 16;
  #pragma unroll
  for (int it = 0; it < 48; ++it) {
    int off = (it*256 + tid)*4;
    *(float4*)(U_s + off) = *(const float4*)(Ugru + off);
  }
  if (tid < 96) *(float4*)(b_s + tid*4) = *(const float4*)(b1 + tid*4);
  for (int i = tid; i < 16*128; i += 256) h_s[i] = 0.f;
  __syncthreads();
  const int tx = tid & 63, tg = tid >> 6;
  for (int t = 0; t < T; ++t) {
    float xp[4][6];
    #pragma unroll
    for (int i=0;i<4;i++) {
      long long base = ((long long)(b0 + tg*4 + i)*T + t)*N3;
      #pragma unroll
      for (int j=0;j<6;j++) xp[i][j] = Xp[base + tx + 64*j];
    }
    float acc[4][6];
    #pragma unroll
    for (int i=0;i<4;i++)
      #pragma unroll
      for (int j=0;j<6;j++) acc[i][j] = 0.f;
    #pragma unroll 2
    for (int k = 0; k < 128; k += 4) {
      float4 h4[4];
      #pragma unroll
      for (int i=0;i<4;i++) h4[i] = *(const float4*)(h_s + (tg*4+i)*128 + k);
      #pragma unroll
      for (int kk=0;kk<4;++kk) {
        float uv[6];
        #pragma unroll
        for (int j=0;j<6;j++) uv[j] = U_s[(k+kk)*N3 + tx + 64*j];
        #pragma unroll
        for (int i=0;i<4;i++) {
          float hv = (&h4[i].x)[kk];
          #pragma unroll
          for (int j=0;j<6;j++) acc[i][j] = fmaf(hv, uv[j], acc[i][j]);
        }
      }
    }
    __syncthreads();
    #pragma unroll
    for (int i=0;i<4;i++) {
      int r = tg*4 + i;
      #pragma unroll
      for (int jj=0;jj<2;++jj) {
        int c = tx + 64*jj;
        float hz = acc[i][jj]   + b_s[c];
        float hr = acc[i][2+jj] + b_s[128+c];
        float hh = acc[i][4+jj] + b_s[256+c];
        float z  = sigf(xp[i][jj]   + hz);
        float rg = sigf(xp[i][2+jj] + hr);
        float hc = tanhf(xp[i][4+jj] + rg*hh);
        float hold = h_s[r*128 + c];
        float hn = z*hold + (1.f - z)*hc;
        h_s[r*128 + c] = hn;
        hs[((long long)(b0 + r)*T + t)*U + c] = hn;
      }
    }
    __syncthreads();
  }
}

// ------------------------------ AUGRU scan ------------------------------
__global__ void augru_scan_kernel(const float* __restrict__ X3) {
  extern __shared__ float sm[];
  float* U_s = sm;            // 128*384
  float* h_s = sm + 128*384;  // 16*128
  const int tid = threadIdx.x;
  const int b0 = blockIdx.x * 16;
  #pragma unroll
  for (int it = 0; it < 48; ++it) {
    int off = (it*256 + tid)*4;
    *(float4*)(U_s + off) = *(const float4*)(g_Uau + off);
  }
  for (int i = tid; i < 16*128; i += 256) h_s[i] = 0.f;
  __syncthreads();
  const int tx = tid & 63, tg = tid >> 6;
  for (int t = 0; t < T; ++t) {
    float xp[4][6], at[4];
    #pragma unroll
    for (int i=0;i<4;i++) {
      long long rowi = (long long)(b0 + tg*4 + i)*T + t;
      at[i] = g_ats[rowi];
      #pragma unroll
      for (int j=0;j<6;j++) xp[i][j] = X3[rowi*N3 + tx + 64*j];
    }
    float acc[4][6];
    #pragma unroll
    for (int i=0;i<4;i++)
      #pragma unroll
      for (int j=0;j<6;j++) acc[i][j] = 0.f;
    #pragma unroll 2
    for (int k = 0; k < 128; k += 4) {
      float4 h4[4];
      #pragma unroll
      for (int i=0;i<4;i++) h4[i] = *(const float4*)(h_s + (tg*4+i)*128 + k);
      #pragma unroll
      for (int kk=0;kk<4;++kk) {
        float uv[6];
        #pragma unroll
        for (int j=0;j<6;j++) uv[j] = U_s[(k+kk)*N3 + tx + 64*j];
        #pragma unroll
        for (int i=0;i<4;i++) {
          float hv = (&h4[i].x)[kk];
          #pragma unroll
          for (int j=0;j<6;j++) acc[i][j] = fmaf(hv, uv[j], acc[i][j]);
        }
      }
    }
    __syncthreads();
    #pragma unroll
    for (int i=0;i<4;i++) {
      int r = tg*4 + i;
      #pragma unroll
      for (int jj=0;jj<2;++jj) {
        int c = tx + 64*jj;
        float u  = sigf(xp[i][jj]   + acc[i][jj]);
        float rg = sigf(xp[i][2+jj] + acc[i][2+jj]);
        float cc = tanhf(xp[i][4+jj] + rg*acc[i][4+jj]);
        float uu = at[i]*u;
        float hold = h_s[r*128 + c];
        h_s[r*128 + c] = (1.f - uu)*hold + uu*cc;
      }
    }
    __syncthreads();
  }
  #pragma unroll
  for (int i=0;i<4;i++) {
    int r = tg*4 + i;
    #pragma unroll
    for (int jj=0;jj<2;++jj) {
      int c = tx + 64*jj;
      g_hfin[(b0 + r)*128 + c] = h_s[r*128 + c];
    }
  }
}

// ------------------------------ attention ------------------------------
// a1 = relu(hs@W1x + (hs*news)@W1D + newsterm); a2 = relu(a1@W2+b2); score = sig(a2@W3+b3)
__global__ void att_kernel(const float* __restrict__ hs, const float* __restrict__ inputs,
                           const float* __restrict__ W2, const float* __restrict__ b2,
                           const float* __restrict__ W3, const float* __restrict__ b3,
                           const float* __restrict__ W1D) {
  extern __shared__ float sm[];
  float* W1x_s = sm;                 // 16384
  float* W1D_s = W1x_s + 16384;      // 16384
  float* W2_s  = W1D_s + 16384;      // 8192
  float* b2_s  = W2_s + 8192;        // 64
  float* W3_s  = b2_s + 64;          // 64
  float* hs_s  = W3_s + 64;          // 4*128
  float* hn_s  = hs_s + 512;         // 4*128
  float* a1_s  = hn_s + 512;         // 4*128
  float* a2_s  = a1_s + 512;         // 4*64
  const int tid = threadIdx.x;       // 512
  for (int i = tid; i < 16384; i += 512) { W1x_s[i] = g_W1x[i]; W1D_s[i] = W1D[i]; }
  for (int i = tid; i < 8192; i += 512) W2_s[i] = W2[i];
  if (tid < 64) { b2_s[tid] = b2[tid]; W3_s[tid] = W3[tid]; }
  __syncthreads();
  const int slot = tid >> 7, j = tid & 127;
  const float b3v = b3[0];
  for (long long base = (long long)blockIdx.x*4; base < BT; base += (long long)gridDim.x*4) {
    long long row = base + slot;
    bool valid = row < BT;
    int b = valid ? (int)(row / T) : 0;
    if (valid) {
      float h  = hs[row*128 + j];
      float nw = inputs[((long long)b*(T+1) + T)*128 + j];
      hs_s[slot*128 + j] = h;
      hn_s[slot*128 + j] = h*nw;
    }
    __syncthreads();
    if (valid) {
      float acc = g_newsterm[b*128 + j];
      #pragma unroll 4
      for (int k=0;k<128;++k)
        acc += hs_s[slot*128+k]*W1x_s[k*128+j] + hn_s[slot*128+k]*W1D_s[k*128+j];
      a1_s[slot*128 + j] = fmaxf(acc, 0.f);
    }
    __syncthreads();
    if (valid && j < 64) {
      float a = b2_s[j];
      #pragma unroll 4
      for (int k=0;k<128;++k) a = fmaf(a1_s[slot*128+k], W2_s[k*64+j], a);
      a2_s[slot*64 + j] = fmaxf(a, 0.f);
    }
    __syncthreads();
    if (valid && j < 32) {
      float s = a2_s[slot*64+j]*W3_s[j] + a2_s[slot*64+j+32]*W3_s[j+32];
      #pragma unroll
      for (int off=16; off>0; off>>=1) s += __shfl_xor_sync(0xffffffffu, s, off);
      if (j == 0) g_ats[row] = sigf(s + b3v);
    }
    __syncthreads();
  }
}

// ------------------------------ head ------------------------------
__global__ void head_kernel(const float* __restrict__ inputs,
                            const float* __restrict__ gamma, const float* __restrict__ beta,
                            const float* __restrict__ mean,  const float* __restrict__ var,
                            const float* __restrict__ W1, const float* __restrict__ bb1,
                            const float* __restrict__ W2, const float* __restrict__ bb2,
                            const float* __restrict__ fW, const float* __restrict__ fb,
                            float* __restrict__ out) {
  extern __shared__ float sm[];
  float* xs  = sm;          // 32*256
  float* y1s = xs + 8192;   // 32*256
  float* y2s = y1s + 8192;  // 32*128
  const int tid = threadIdx.x;   // 256
  const int b0 = blockIdx.x * 32;
  for (int r = 0; r < 32; ++r) {
    int k = tid;
    int bb = b0 + r;
    float v = (k < 128) ? g_hfin[bb*128 + k]
                        : inputs[((long long)bb*(T+1) + T)*128 + (k - 128)];
    float nv = (v - mean[k]) * rsqrtf(var[k] + BN_EPS) * gamma[k] + beta[k];
    xs[r*256 + k] = nv;
  }
  __syncthreads();
  {
    float acc[32];
    #pragma unroll
    for (int r=0;r<32;r++) acc[r] = bb1[tid];
    for (int k=0;k<256;++k) {
      float w = W1[k*256 + tid];
      #pragma unroll
      for (int r=0;r<32;r++) acc[r] = fmaf(xs[r*256+k], w, acc[r]);
    }
    #pragma unroll
    for (int r=0;r<32;r++) {
      float v = acc[r];
      y1s[r*256 + tid] = v >= 0.f ? v : LEAKY*v;
    }
  }
  __syncthreads();
  if (tid < 128) {
    float acc[32];
    #pragma unroll
    for (int r=0;r<32;r++) acc[r] = bb2[tid];
    for (int k=0;k<256;++k) {
      float w = W2[k*128 + tid];
      #pragma unroll
      for (int r=0;r<32;r++) acc[r] = fmaf(y1s[r*256+k], w, acc[r]);
    }
    #pragma unroll
    for (int r=0;r<32;r++) {
      float v = acc[r];
      y2s[r*128 + tid] = v >= 0.f ? v : LEAKY*v;
    }
  }
  __syncthreads();
  if (tid < 32) {
    float acc = fb[0];
    for (int k=0;k<128;++k) acc = fmaf(y2s[tid*128+k], fW[k], acc);
    out[b0 + tid] = sigf(acc);
  }
}

// ------------------------------ launch ------------------------------
extern "C" void kernel_launch(void* const* d_in, const int* in_sizes, int n_in,
                              void* d_out, int out_size) {
  (void)in_sizes; (void)n_in; (void)out_size;
  const float* inputs  = (const float*)d_in[0];
  const float* gru_W   = (const float*)d_in[1];
  const float* gru_U   = (const float*)d_in[2];
  const float* gru_b   = (const float*)d_in[3];
  const float* att_W1  = (const float*)d_in[4];
  const float* att_b1  = (const float*)d_in[5];
  const float* att_W2  = (const float*)d_in[6];
  const float* att_b2  = (const float*)d_in[7];
  const float* att_W3  = (const float*)d_in[8];
  const float* att_b3  = (const float*)d_in[9];
  const float* au_Wu   = (const float*)d_in[10];
  const float* au_bu   = (const float*)d_in[11];
  const float* au_Uu   = (const float*)d_in[12];
  const float* au_Wr   = (const float*)d_in[13];
  const float* au_br   = (const float*)d_in[14];
  const float* au_Ur   = (const float*)d_in[15];
  const float* au_Wc   = (const float*)d_in[16];
  const float* au_bc   = (const float*)d_in[17];
  const float* au_Uc   = (const float*)d_in[18];
  const float* bn_gamma= (const float*)d_in[19];
  const float* bn_beta = (const float*)d_in[20];
  const float* bn_mean = (const float*)d_in[21];
  const float* bn_var  = (const float*)d_in[22];
  const float* d_W1    = (const float*)d_in[23];
  const float* d_b1    = (const float*)d_in[24];
  const float* d_W2    = (const float*)d_in[25];
  const float* d_b2    = (const float*)d_in[26];
  const float* f_W     = (const float*)d_in[27];
  const float* f_b     = (const float*)d_in[28];
  float* out = (float*)d_out;

  const size_t sm_gemm = (64*132 + 128*128)*sizeof(float);                // 99 KB
  const size_t sm_scan = (128*384 + 16*128 + 384)*sizeof(float);          // 206 KB
  const size_t sm_au   = (128*384 + 16*128)*sizeof(float);                // 205 KB
  const size_t sm_att  = (16384*2 + 8192 + 64 + 64 + 512*3 + 256)*sizeof(float); // 172 KB
  const size_t sm_head = (8192*2 + 4096)*sizeof(float);                   // 82 KB
  cudaFuncSetAttribute(gemm_k128,        cudaFuncAttributeMaxDynamicSharedMemorySize, (int)sm_gemm);
  cudaFuncSetAttribute(gru_scan_kernel,  cudaFuncAttributeMaxDynamicSharedMemorySize, (int)sm_scan);
  cudaFuncSetAttribute(augru_scan_kernel,cudaFuncAttributeMaxDynamicSharedMemorySize, (int)sm_au);
  cudaFuncSetAttribute(att_kernel,       cudaFuncAttributeMaxDynamicSharedMemorySize, (int)sm_att);
  cudaFuncSetAttribute(head_kernel,      cudaFuncAttributeMaxDynamicSharedMemorySize, (int)sm_head);

  float *p_Xp, *p_hs, *p_X3, *p_newsterm, *p_Wau, *p_bau, *p_W1bc;
  cudaGetSymbolAddress((void**)&p_Xp,       g_Xp);
  cudaGetSymbolAddress((void**)&p_hs,       g_hs);
  cudaGetSymbolAddress((void**)&p_X3,       g_X3);
  cudaGetSymbolAddress((void**)&p_newsterm, g_newsterm);
  cudaGetSymbolAddress((void**)&p_Wau,      g_Wau);
  cudaGetSymbolAddress((void**)&p_bau,      g_bau);
  cudaGetSymbolAddress((void**)&p_W1bc,     g_W1bc);

  // 1) pack AU weights (input + recurrent) + attention folded weights
  prep_kernel<<<192, 256>>>(au_Wu, au_bu, au_Wr, au_br, au_Wc, au_bc,
                            au_Uu, au_Ur, au_Uc, att_W1);
  // 2) GRU input projection:  Xp = hist @ gru_W + gru_b[0]
  gemm_k128<<<dim3(BT/64, 3), 256, sm_gemm>>>(inputs, T, (long long)(T+1)*128, gru_W, gru_b, p_Xp);
  // 3) per-batch news term for attention layer 1
  gemm_k128<<<dim3(B/64, 1), 256, sm_gemm>>>(inputs + (long long)T*128, 1, (long long)(T+1)*128,
                                             p_W1bc, att_b1, p_newsterm);
  // 4) GRU recurrence -> hs
  gru_scan_kernel<<<B/16, 256, sm_scan>>>(p_Xp, gru_U, gru_b + 384, p_hs);
  // 5) attention scores
  att_kernel<<<148, 512, sm_att>>>(p_hs, inputs, att_W2, att_b2, att_W3, att_b3,
                                   att_W1 + 3*128*128);
  // 6) AUGRU input projections: X3 = hs @ [Wu|Wr|Wc] + [bu|br|bc]
  gemm_k128<<<dim3(BT/64, 3), 256, sm_gemm>>>(p_hs, 1<<30, 0LL, p_Wau, p_bau, p_X3);
  // 7) AUGRU recurrence -> hfin
  augru_scan_kernel<<<B/16, 256, sm_au>>>(p_X3);
  // 8) BN + dense head -> out
  head_kernel<<<B/32, 256, sm_head>>>(inputs, bn_gamma, bn_beta, bn_mean, bn_var,
                                      d_W1, d_b1, d_W2, d_b2, f_W, f_b, out);
}

// round 3
// speedup vs baseline: 1.4418x; 1.4418x over previous
#include <cuda_runtime.h>
#include <math.h>
#include <stdint.h>

#define B  4096
#define T  50
#define U  128
#define N3 384
#define BT (B*T)
#define BN_EPS 1e-3f
#define LEAKY  3e-4f

// ------------ scratch (device globals; no allocation allowed) ------------
__device__ float g_Xp[BT*N3];        // GRU input projection; later reused as Zcat (BT x 256)
__device__ float g_hs[BT*U];         // GRU hidden states
__device__ float g_X3[BT*N3];        // a1 (BT x 128), then AUGRU input projections
__device__ float g_ats[BT];          // attention scores
__device__ float g_hfin[B*U];        // AUGRU final state
__device__ float g_newsterm[B*U];    // news@(W1B+W1C)+b1
__device__ float g_Wau[U*N3];        // packed input  [Wu|Wr|Wc]
__device__ float g_Uau[U*N3];        // packed recur  [Uu|Ur|Uc]
__device__ float g_bau[N3];          // packed [bu|br|bc]
__device__ float g_Wcat[2*U*U];      // [W1A-W1B ; W1D]  (256 x 128)
__device__ float g_W1bc[U*U];        // W1B + W1C

__device__ __forceinline__ float sigf(float x){ return 1.f/(1.f+expf(-x)); }
__device__ __forceinline__ float tf32r(float f){
  uint32_t r; asm("cvt.rna.tf32.f32 %0, %1;" : "=r"(r) : "f"(f));
  return __uint_as_float(r);
}
__device__ __forceinline__ void mma8(float* d, const uint32_t* a, const uint32_t* b){
  asm volatile("mma.sync.aligned.m16n8k8.row.col.f32.tf32.tf32.f32 "
               "{%0,%1,%2,%3}, {%4,%5,%6,%7}, {%8,%9}, {%0,%1,%2,%3};"
               : "+f"(d[0]), "+f"(d[1]), "+f"(d[2]), "+f"(d[3])
               : "r"(a[0]), "r"(a[1]), "r"(a[2]), "r"(a[3]), "r"(b[0]), "r"(b[1]));
}

// ------------------------------- prep -------------------------------
__global__ void prep_kernel(const float* __restrict__ Wu, const float* __restrict__ bu,
                            const float* __restrict__ Wr, const float* __restrict__ br,
                            const float* __restrict__ Wc, const float* __restrict__ bc,
                            const float* __restrict__ Uu, const float* __restrict__ Ur,
                            const float* __restrict__ Uc,
                            const float* __restrict__ attW1) {
  int id = blockIdx.x*blockDim.x + threadIdx.x;
  if (id < U*N3) {
    int k = id / N3, c = id % N3;
    float w, u;
    if (c < 128)      { w = Wu[k*128 + c];       u = Uu[k*128 + c]; }
    else if (c < 256) { w = Wr[k*128 + (c-128)]; u = Ur[k*128 + (c-128)]; }
    else              { w = Wc[k*128 + (c-256)]; u = Uc[k*128 + (c-256)]; }
    g_Wau[id] = w;
    g_Uau[id] = u;
  }
  if (id < N3)
    g_bau[id] = (id < 128) ? bu[id] : (id < 256 ? br[id-128] : bc[id-256]);
  if (id < 2*U*U) {
    int k = id / 128, c = id % 128;
    float v;
    if (k < 128) v = attW1[k*128 + c] - attW1[U*U + k*128 + c];     // W1A - W1B
    else         v = attW1[3*U*U + (k-128)*128 + c];                // W1D
    g_Wcat[id] = v;
  }
  if (id < U*U)
    g_W1bc[id] = attW1[U*U + id] + attW1[2*U*U + id];
}

// --------------------- tf32 tensor-core GEMM ---------------------
// C[m, c0..c0+128) = sum_kc A_row(m)[kc*128 ..] @ W[(kc*128..)*ldw + ...]  + epilogue
// A row m at A + (m/P)*GS + (m%P)*RS.  mode 0: +bias.  mode 1: relu(acc + nterm[(m/T)*128+c]).
__global__ void gemm_tf32(const float* __restrict__ A, int P, long long GS, int RS,
                          int kchunks, const float* __restrict__ W, int ldw,
                          const float* __restrict__ bias, float* __restrict__ C, int ldc,
                          int mode, const float* __restrict__ nterm) {
  extern __shared__ float sm[];
  float* As = sm;               // 64 x 132
  float* Bs = sm + 64*132;      // 128 x 136
  const int m0 = blockIdx.x * 64;
  const int c0 = blockIdx.y * 128;
  const int tid = threadIdx.x;          // 256
  const int kq = tid >> 5, cq = tid & 31;
  const int lane = tid & 31, wid = tid >> 5;
  const int wm = wid & 1, wn = wid >> 1;          // warp tile: 32 rows x 32 cols
  const int g = lane >> 2, t4 = lane & 3;

  float acc[2][4][4];
  #pragma unroll
  for (int mt=0;mt<2;mt++)
    #pragma unroll
    for (int nt=0;nt<4;nt++)
      #pragma unroll
      for (int q=0;q<4;q++) acc[mt][nt][q] = 0.f;

  for (int kc = 0; kc < kchunks; ++kc) {
    if (kc) __syncthreads();
    #pragma unroll
    for (int it = 0; it < 8; ++it) {
      int r = kq + 8*it;
      int m = m0 + r;
      const float* ap = A + (long long)(m/P)*GS + (long long)(m%P)*RS + kc*128;
      float4 v = *(const float4*)(ap + 4*cq);
      float* dst = As + r*132 + 4*cq;
      dst[0]=tf32r(v.x); dst[1]=tf32r(v.y); dst[2]=tf32r(v.z); dst[3]=tf32r(v.w);
    }
    #pragma unroll
    for (int it = 0; it < 16; ++it) {
      int k = kq + 8*it;
      float4 v = *(const float4*)(W + (long long)(kc*128 + k)*ldw + c0 + 4*cq);
      float* dst = Bs + k*136 + 4*cq;
      dst[0]=tf32r(v.x); dst[1]=tf32r(v.y); dst[2]=tf32r(v.z); dst[3]=tf32r(v.w);
    }
    __syncthreads();
    #pragma unroll
    for (int k8 = 0; k8 < 16; ++k8) {
      const int kb = k8*8;
      uint32_t a[2][4];
      #pragma unroll
      for (int mt=0;mt<2;mt++) {
        int rb = wm*32 + mt*16 + g;
        a[mt][0] = __float_as_uint(As[rb*132     + kb + t4]);
        a[mt][1] = __float_as_uint(As[(rb+8)*132 + kb + t4]);
        a[mt][2] = __float_as_uint(As[rb*132     + kb + t4 + 4]);
        a[mt][3] = __float_as_uint(As[(rb+8)*132 + kb + t4 + 4]);
      }
      uint32_t b[4][2];
      #pragma unroll
      for (int nt=0;nt<4;nt++) {
        int nb = wn*32 + nt*8 + g;
        b[nt][0] = __float_as_uint(Bs[(kb+t4)*136   + nb]);
        b[nt][1] = __float_as_uint(Bs[(kb+t4+4)*136 + nb]);
      }
      #pragma unroll
      for (int mt=0;mt<2;mt++)
        #pragma unroll
        for (int nt=0;nt<4;nt++)
          mma8(acc[mt][nt], a[mt], b[nt]);
    }
  }
  // epilogue
  #pragma unroll
  for (int mt=0;mt<2;mt++) {
    int row0 = m0 + wm*32 + mt*16 + g;
    #pragma unroll
    for (int nt=0;nt<4;nt++) {
      int col = c0 + wn*32 + nt*8 + 2*t4;
      #pragma unroll
      for (int h=0; h<2; ++h) {
        int row = row0 + 8*h;
        float v0 = acc[mt][nt][2*h+0], v1 = acc[mt][nt][2*h+1];
        if (mode == 0) { v0 += bias[col]; v1 += bias[col+1]; }
        else {
          const float* np = nterm + (long long)(row / T)*128;
          v0 = fmaxf(v0 + np[col],   0.f);
          v1 = fmaxf(v1 + np[col+1], 0.f);
        }
        float2 o = {v0, v1};
        *(float2*)(C + (long long)row*ldc + col) = o;
      }
    }
  }
}

// ------------------------------ GRU scan (512 thr, 16 rows) ------------------------------
__global__ void gru_scan_kernel(const float* __restrict__ Xp, const float* __restrict__ Ugru,
                                const float* __restrict__ b1, float* __restrict__ hs) {
  extern __shared__ float sm[];
  float* U_s = sm;            // 128*384
  float* h_s = sm + 128*384;  // 16*128
  float* b_s = h_s + 16*128;  // 384
  const int tid = threadIdx.x;      // 512
  const int b0 = blockIdx.x * 16;
  #pragma unroll
  for (int it = 0; it < 24; ++it) {
    int off = (it*512 + tid)*4;
    *(float4*)(U_s + off) = *(const float4*)(Ugru + off);
  }
  if (tid < 96) *(float4*)(b_s + tid*4) = *(const float4*)(b1 + tid*4);
  for (int i = tid; i < 16*128; i += 512) h_s[i] = 0.f;
  __syncthreads();
  const int tx = tid & 63, tg = tid >> 6;   // 8 groups x 2 rows
  for (int t = 0; t < T; ++t) {
    float xp[2][6];
    #pragma unroll
    for (int i=0;i<2;i++) {
      long long base = ((long long)(b0 + tg*2 + i)*T + t)*N3;
      #pragma unroll
      for (int j=0;j<6;j++) xp[i][j] = Xp[base + tx + 64*j];
    }
    float acc[2][6];
    #pragma unroll
    for (int i=0;i<2;i++)
      #pragma unroll
      for (int j=0;j<6;j++) acc[i][j] = 0.f;
    #pragma unroll 2
    for (int k = 0; k < 128; k += 4) {
      float4 h4[2];
      #pragma unroll
      for (int i=0;i<2;i++) h4[i] = *(const float4*)(h_s + (tg*2+i)*128 + k);
      #pragma unroll
      for (int kk=0;kk<4;++kk) {
        float uv[6];
        #pragma unroll
        for (int j=0;j<6;j++) uv[j] = U_s[(k+kk)*N3 + tx + 64*j];
        #pragma unroll
        for (int i=0;i<2;i++) {
          float hv = (&h4[i].x)[kk];
          #pragma unroll
          for (int j=0;j<6;j++) acc[i][j] = fmaf(hv, uv[j], acc[i][j]);
        }
      }
    }
    __syncthreads();
    #pragma unroll
    for (int i=0;i<2;i++) {
      int r = tg*2 + i;
      #pragma unroll
      for (int jj=0;jj<2;++jj) {
        int c = tx + 64*jj;
        float z  = sigf(xp[i][jj]   + acc[i][jj]   + b_s[c]);
        float rg = sigf(xp[i][2+jj] + acc[i][2+jj] + b_s[128+c]);
        float hc = tanhf(xp[i][4+jj] + rg*(acc[i][4+jj] + b_s[256+c]));
        float hold = h_s[r*128 + c];
        float hn = z*hold + (1.f - z)*hc;
        h_s[r*128 + c] = hn;
        hs[((long long)(b0 + r)*T + t)*U + c] = hn;
      }
    }
    __syncthreads();
  }
}

// ------------------------------ AUGRU scan (512 thr) ------------------------------
__global__ void augru_scan_kernel(const float* __restrict__ X3) {
  extern __shared__ float sm[];
  float* U_s = sm;            // 128*384
  float* h_s = sm + 128*384;  // 16*128
  const int tid = threadIdx.x;   // 512
  const int b0 = blockIdx.x * 16;
  #pragma unroll
  for (int it = 0; it < 24; ++it) {
    int off = (it*512 + tid)*4;
    *(float4*)(U_s + off) = *(const float4*)(g_Uau + off);
  }
  for (int i = tid; i < 16*128; i += 512) h_s[i] = 0.f;
  __syncthreads();
  const int tx = tid & 63, tg = tid >> 6;
  for (int t = 0; t < T; ++t) {
    float xp[2][6], at[2];
    #pragma unroll
    for (int i=0;i<2;i++) {
      long long rowi = (long long)(b0 + tg*2 + i)*T + t;
      at[i] = g_ats[rowi];
      #pragma unroll
      for (int j=0;j<6;j++) xp[i][j] = X3[rowi*N3 + tx + 64*j];
    }
    float acc[2][6];
    #pragma unroll
    for (int i=0;i<2;i++)
      #pragma unroll
      for (int j=0;j<6;j++) acc[i][j] = 0.f;
    #pragma unroll 2
    for (int k = 0; k < 128; k += 4) {
      float4 h4[2];
      #pragma unroll
      for (int i=0;i<2;i++) h4[i] = *(const float4*)(h_s + (tg*2+i)*128 + k);
      #pragma unroll
      for (int kk=0;kk<4;++kk) {
        float uv[6];
        #pragma unroll
        for (int j=0;j<6;j++) uv[j] = U_s[(k+kk)*N3 + tx + 64*j];
        #pragma unroll
        for (int i=0;i<2;i++) {
          float hv = (&h4[i].x)[kk];
          #pragma unroll
          for (int j=0;j<6;j++) acc[i][j] = fmaf(hv, uv[j], acc[i][j]);
        }
      }
    }
    __syncthreads();
    #pragma unroll
    for (int i=0;i<2;i++) {
      int r = tg*2 + i;
      #pragma unroll
      for (int jj=0;jj<2;++jj) {
        int c = tx + 64*jj;
        float u  = sigf(xp[i][jj]   + acc[i][jj]);
        float rg = sigf(xp[i][2+jj] + acc[i][2+jj]);
        float cc = tanhf(xp[i][4+jj] + rg*acc[i][4+jj]);
        float uu = at[i]*u;
        float hold = h_s[r*128 + c];
        h_s[r*128 + c] = (1.f - uu)*hold + uu*cc;
      }
    }
    __syncthreads();
  }
  #pragma unroll
  for (int i=0;i<2;i++) {
    int r = tg*2 + i;
    #pragma unroll
    for (int jj=0;jj<2;++jj) {
      int c = tx + 64*jj;
      g_hfin[(b0 + r)*128 + c] = h_s[r*128 + c];
    }
  }
}

// ------------------------------ Zcat = [hs | hs*news] ------------------------------
__global__ void zcat_kernel(const float* __restrict__ hs, const float* __restrict__ inputs,
                            float* __restrict__ Z) {
  long long idx = (long long)blockIdx.x*256 + threadIdx.x;   // over BT*32
  long long row = idx >> 5;
  int q = (int)(idx & 31);
  int b = (int)(row / T);
  float4 h  = *(const float4*)(hs + row*128 + 4*q);
  float4 nw = *(const float4*)(inputs + ((long long)b*(T+1) + T)*128 + 4*q);
  *(float4*)(Z + row*256 + 4*q) = h;
  float4 p; p.x=h.x*nw.x; p.y=h.y*nw.y; p.z=h.z*nw.z; p.w=h.w*nw.w;
  *(float4*)(Z + row*256 + 128 + 4*q) = p;
}

// ------------------------------ attention layer2 + score ------------------------------
// a2 = relu(a1@W2 + b2) (64 cols), score = sigmoid(a2@W3 + b3)
__global__ void att2_kernel(const float* __restrict__ a1, const float* __restrict__ W2,
                            const float* __restrict__ b2, const float* __restrict__ W3,
                            const float* __restrict__ b3) {
  extern __shared__ float sm[];
  float* a1s = sm;            // 64 x 132
  float* a2s = sm + 64*132;   // 64 x 68
  float* W3s = a2s + 64*68;   // 64
  const int tid = threadIdx.x;   // 256
  const long long m0 = (long long)blockIdx.x * 64;
  #pragma unroll
  for (int it = 0; it < 8; ++it) {
    int idx = it*256 + tid;
    int r = idx >> 5, c4 = idx & 31;
    float4 v = *(const float4*)(a1 + (m0 + r)*128 + 4*c4);
    *(float4*)(a1s + r*132 + 4*c4) = v;
  }
  if (tid < 64) W3s[tid] = W3[tid];
  const int c = tid >> 2, rg = tid & 3;
  float w[32];
  #pragma unroll
  for (int kk=0;kk<32;kk++) w[kk] = W2[(rg*32 + kk)*64 + c];
  const float b2c = b2[c];
  __syncthreads();
  for (int r = 0; r < 64; ++r) {
    const float4* ap = (const float4*)(a1s + r*132 + rg*32);
    float dot = 0.f;
    #pragma unroll
    for (int q=0;q<8;q++) {
      float4 v = ap[q];
      dot = fmaf(v.x, w[4*q+0], dot);
      dot = fmaf(v.y, w[4*q+1], dot);
      dot = fmaf(v.z, w[4*q+2], dot);
      dot = fmaf(v.w, w[4*q+3], dot);
    }
    dot += __shfl_xor_sync(0xffffffffu, dot, 1);
    dot += __shfl_xor_sync(0xffffffffu, dot, 2);
    if (rg == 0) a2s[r*68 + c] = fmaxf(dot + b2c, 0.f);
  }
  __syncthreads();
  if (tid < 64) {
    float accv = b3[0];
    #pragma unroll 8
    for (int cc=0; cc<64; ++cc) accv = fmaf(a2s[tid*68 + cc], W3s[cc], accv);
    g_ats[m0 + tid] = sigf(accv);
  }
}

// ------------------------------ head ------------------------------
__global__ void head_kernel(const float* __restrict__ inputs,
                            const float* __restrict__ gamma, const float* __restrict__ beta,
                            const float* __restrict__ mean,  const float* __restrict__ var,
                            const float* __restrict__ W1, const float* __restrict__ bb1,
                            const float* __restrict__ W2, const float* __restrict__ bb2,
                            const float* __restrict__ fW, const float* __restrict__ fb,
                            float* __restrict__ out) {
  extern __shared__ float sm[];
  float* xs  = sm;          // 32*256
  float* y1s = xs + 8192;   // 32*256
  float* y2s = y1s + 8192;  // 32*128
  const int tid = threadIdx.x;   // 256
  const int b0 = blockIdx.x * 32;
  for (int r = 0; r < 32; ++r) {
    int k = tid;
    int bb = b0 + r;
    float v = (k < 128) ? g_hfin[bb*128 + k]
                        : inputs[((long long)bb*(T+1) + T)*128 + (k - 128)];
    float nv = (v - mean[k]) * rsqrtf(var[k] + BN_EPS) * gamma[k] + beta[k];
    xs[r*256 + k] = nv;
  }
  __syncthreads();
  {
    float acc[32];
    #pragma unroll
    for (int r=0;r<32;r++) acc[r] = bb1[tid];
    for (int k=0;k<256;++k) {
      float w = W1[k*256 + tid];
      #pragma unroll
      for (int r=0;r<32;r++) acc[r] = fmaf(xs[r*256+k], w, acc[r]);
    }
    #pragma unroll
    for (int r=0;r<32;r++) {
      float v = acc[r];
      y1s[r*256 + tid] = v >= 0.f ? v : LEAKY*v;
    }
  }
  __syncthreads();
  if (tid < 128) {
    float acc[32];
    #pragma unroll
    for (int r=0;r<32;r++) acc[r] = bb2[tid];
    for (int k=0;k<256;++k) {
      float w = W2[k*128 + tid];
      #pragma unroll
      for (int r=0;r<32;r++) acc[r] = fmaf(y1s[r*256+k], w, acc[r]);
    }
    #pragma unroll
    for (int r=0;r<32;r++) {
      float v = acc[r];
      y2s[r*128 + tid] = v >= 0.f ? v : LEAKY*v;
    }
  }
  __syncthreads();
  if (tid < 32) {
    float acc = fb[0];
    for (int k=0;k<128;++k) acc = fmaf(y2s[tid*128+k], fW[k], acc);
    out[b0 + tid] = sigf(acc);
  }
}

// ------------------------------ launch ------------------------------
extern "C" void kernel_launch(void* const* d_in, const int* in_sizes, int n_in,
                              void* d_out, int out_size) {
  (void)in_sizes; (void)n_in; (void)out_size;
  const float* inputs  = (const float*)d_in[0];
  const float* gru_W   = (const float*)d_in[1];
  const float* gru_U   = (const float*)d_in[2];
  const float* gru_b   = (const float*)d_in[3];
  const float* att_W1  = (const float*)d_in[4];
  const float* att_b1  = (const float*)d_in[5];
  const float* att_W2  = (const float*)d_in[6];
  const float* att_b2  = (const float*)d_in[7];
  const float* att_W3  = (const float*)d_in[8];
  const float* att_b3  = (const float*)d_in[9];
  const float* au_Wu   = (const float*)d_in[10];
  const float* au_bu   = (const float*)d_in[11];
  const float* au_Uu   = (const float*)d_in[12];
  const float* au_Wr   = (const float*)d_in[13];
  const float* au_br   = (const float*)d_in[14];
  const float* au_Ur   = (const float*)d_in[15];
  const float* au_Wc   = (const float*)d_in[16];
  const float* au_bc   = (const float*)d_in[17];
  const float* au_Uc   = (const float*)d_in[18];
  const float* bn_gamma= (const float*)d_in[19];
  const float* bn_beta = (const float*)d_in[20];
  const float* bn_mean = (const float*)d_in[21];
  const float* bn_var  = (const float*)d_in[22];
  const float* d_W1    = (const float*)d_in[23];
  const float* d_b1    = (const float*)d_in[24];
  const float* d_W2    = (const float*)d_in[25];
  const float* d_b2    = (const float*)d_in[26];
  const float* f_W     = (const float*)d_in[27];
  const float* f_b     = (const float*)d_in[28];
  float* out = (float*)d_out;

  const size_t sm_gemm = (64*132 + 128*136)*sizeof(float);                // ~103 KB
  const size_t sm_scan = (128*384 + 16*128 + 384)*sizeof(float);          // ~206 KB
  const size_t sm_au   = (128*384 + 16*128)*sizeof(float);                // ~205 KB
  const size_t sm_att2 = (64*132 + 64*68 + 64)*sizeof(float);             // ~52 KB
  const size_t sm_head = (8192*2 + 4096)*sizeof(float);                   // 82 KB
  cudaFuncSetAttribute(gemm_tf32,        cudaFuncAttributeMaxDynamicSharedMemorySize, (int)sm_gemm);
  cudaFuncSetAttribute(gru_scan_kernel,  cudaFuncAttributeMaxDynamicSharedMemorySize, (int)sm_scan);
  cudaFuncSetAttribute(augru_scan_kernel,cudaFuncAttributeMaxDynamicSharedMemorySize, (int)sm_au);
  cudaFuncSetAttribute(att2_kernel,      cudaFuncAttributeMaxDynamicSharedMemorySize, (int)sm_att2);
  cudaFuncSetAttribute(head_kernel,      cudaFuncAttributeMaxDynamicSharedMemorySize, (int)sm_head);

  float *p_Xp, *p_hs, *p_X3, *p_newsterm, *p_Wau, *p_bau, *p_Wcat, *p_W1bc;
  cudaGetSymbolAddress((void**)&p_Xp,       g_Xp);
  cudaGetSymbolAddress((void**)&p_hs,       g_hs);
  cudaGetSymbolAddress((void**)&p_X3,       g_X3);
  cudaGetSymbolAddress((void**)&p_newsterm, g_newsterm);
  cudaGetSymbolAddress((void**)&p_Wau,      g_Wau);
  cudaGetSymbolAddress((void**)&p_bau,      g_bau);
  cudaGetSymbolAddress((void**)&p_Wcat,     g_Wcat);
  cudaGetSymbolAddress((void**)&p_W1bc,     g_W1bc);

  // 1) pack AU weights + attention folded weights
  prep_kernel<<<192, 256>>>(au_Wu, au_bu, au_Wr, au_br, au_Wc, au_bc,
                            au_Uu, au_Ur, au_Uc, att_W1);
  // 2) Xp = hist @ gru_W + gru_b[0]   (tf32 MMA)
  gemm_tf32<<<dim3(BT/64, 3), 256, sm_gemm>>>(inputs, T, (long long)(T+1)*128, 128, 1,
                                              gru_W, 384, gru_b, p_Xp, 384, 0, nullptr);
  // 3) newsterm = news @ (W1B+W1C) + b1
  gemm_tf32<<<dim3(B/64, 1), 256, sm_gemm>>>(inputs + (long long)T*128, 1, (long long)(T+1)*128, 128, 1,
                                             p_W1bc, 128, att_b1, p_newsterm, 128, 0, nullptr);
  // 4) GRU recurrence -> hs
  gru_scan_kernel<<<B/16, 512, sm_scan>>>(p_Xp, gru_U, gru_b + 384, p_hs);
  // 5) Zcat = [hs | hs*news]  (into g_Xp, free now)
  zcat_kernel<<<BT*32/256, 256>>>(p_hs, inputs, p_Xp);
  // 6) a1 = relu(Zcat @ Wcat + newsterm)   (into g_X3)
  gemm_tf32<<<dim3(BT/64, 1), 256, sm_gemm>>>(p_Xp, 1<<30, 0LL, 256, 2,
                                              p_Wcat, 128, nullptr, p_X3, 128, 1, p_newsterm);
  // 7) attention layer2 + score -> g_ats
  att2_kernel<<<BT/64, 256, sm_att2>>>(p_X3, att_W2, att_b2, att_W3, att_b3);
  // 8) X3 = hs @ [Wu|Wr|Wc] + [bu|br|bc]
  gemm_tf32<<<dim3(BT/64, 3), 256, sm_gemm>>>(p_hs, 1<<30, 0LL, 128, 1,
                                              p_Wau, 384, p_bau, p_X3, 384, 0, nullptr);
  // 9) AUGRU recurrence -> hfin
  augru_scan_kernel<<<B/16, 512, sm_au>>>(p_X3);
  // 10) BN + dense head -> out
  head_kernel<<<B/32, 256, sm_head>>>(inputs, bn_gamma, bn_beta, bn_mean, bn_var,
                                      d_W1, d_b1, d_W2, d_b2, f_W, f_b, out);
}

// round 4
// speedup vs baseline: 2.3595x; 1.6365x over previous
#include <cuda_runtime.h>
#include <math.h>
#include <stdint.h>

#define B  4096
#define T  50
#define U  128
#define N3 384
#define BT (B*T)
#define BN_EPS 1e-3f
#define LEAKY  3e-4f

// ------------ scratch (device globals; no allocation allowed) ------------
__device__ float g_Xp[BT*N3];        // GRU input projection; later reused as Zcat (BT x 256)
__device__ float g_hs[BT*U];         // GRU hidden states
__device__ float g_X3[BT*N3];        // a1 (BT x 128), then AUGRU input projections
__device__ float g_ats[BT];          // attention scores
__device__ float g_hfin[B*U];        // AUGRU final state
__device__ float g_newsterm[B*U];    // news@(W1B+W1C)+b1
__device__ float g_Wau[U*N3];        // packed input  [Wu|Wr|Wc]
__device__ float g_Uau[U*N3];        // packed recur  [Uu|Ur|Uc]
__device__ float g_bau[N3];          // packed [bu|br|bc]
__device__ float g_Wcat[2*U*U];      // [W1A-W1B ; W1D]  (256 x 128)
__device__ float g_W1bc[U*U];        // W1B + W1C
__device__ float g_Upack_gru[128*N3];// fragment-ordered gru_U (tf32)
__device__ float g_Upack_au[128*N3]; // fragment-ordered [Uu|Ur|Uc] (tf32)

__device__ __forceinline__ float sigf(float x){ return 1.f/(1.f+expf(-x)); }
__device__ __forceinline__ float sig_(float x){ return __fdividef(1.f, 1.f + __expf(-x)); }
__device__ __forceinline__ float tanh_(float x){ return 1.f - 2.f*__fdividef(1.f, 1.f + __expf(2.f*x)); }
__device__ __forceinline__ float tf32r(float f){
  uint32_t r; asm("cvt.rna.tf32.f32 %0, %1;" : "=r"(r) : "f"(f));
  return __uint_as_float(r);
}
__device__ __forceinline__ void mma8(float* d, const uint32_t* a, const uint32_t* b){
  asm volatile("mma.sync.aligned.m16n8k8.row.col.f32.tf32.tf32.f32 "
               "{%0,%1,%2,%3}, {%4,%5,%6,%7}, {%8,%9}, {%0,%1,%2,%3};"
               : "+f"(d[0]), "+f"(d[1]), "+f"(d[2]), "+f"(d[3])
               : "r"(a[0]), "r"(a[1]), "r"(a[2]), "r"(a[3]), "r"(b[0]), "r"(b[1]));
}

// ------------------------------- prep -------------------------------
__global__ void prep_kernel(const float* __restrict__ Wu, const float* __restrict__ bu,
                            const float* __restrict__ Wr, const float* __restrict__ br,
                            const float* __restrict__ Wc, const float* __restrict__ bc,
                            const float* __restrict__ Uu, const float* __restrict__ Ur,
                            const float* __restrict__ Uc,
                            const float* __restrict__ attW1) {
  int id = blockIdx.x*blockDim.x + threadIdx.x;
  if (id < U*N3) {
    int k = id / N3, c = id % N3;
    float w, u;
    if (c < 128)      { w = Wu[k*128 + c];       u = Uu[k*128 + c]; }
    else if (c < 256) { w = Wr[k*128 + (c-128)]; u = Ur[k*128 + (c-128)]; }
    else              { w = Wc[k*128 + (c-256)]; u = Uc[k*128 + (c-256)]; }
    g_Wau[id] = w;
    g_Uau[id] = u;
  }
  if (id < N3)
    g_bau[id] = (id < 128) ? bu[id] : (id < 256 ? br[id-128] : bc[id-256]);
  if (id < 2*U*U) {
    int k = id / 128, c = id % 128;
    float v;
    if (k < 128) v = attW1[k*128 + c] - attW1[U*U + k*128 + c];     // W1A - W1B
    else         v = attW1[3*U*U + (k-128)*128 + c];                // W1D
    g_Wcat[id] = v;
  }
  if (id < U*U)
    g_W1bc[id] = attW1[U*U + id] + attW1[2*U*U + id];
}

// --------------- pack recurrent weights fragment-ordered ---------------
// P[((k8*24 + tp)*32 + lane)*4 + q]: tile=2*tp+(q>>1), reg=q&1,
//   k = k8*8 + (lane&3) + 4*reg,  n = tile*8 + (lane>>2)
__global__ void pack_frag_kernel(const float* __restrict__ Um, float* __restrict__ P) {
  int idx = blockIdx.x*256 + threadIdx.x;   // 49152 total
  int q = idx & 3, lane = (idx >> 2) & 31;
  int tp = (idx >> 7) % 24, k8 = (idx >> 7) / 24;
  int tile = 2*tp + (q >> 1), r = q & 1;
  int k = k8*8 + (lane & 3) + 4*r;
  int n = tile*8 + (lane >> 2);
  P[idx] = tf32r(Um[k*N3 + n]);
}

// --------------------- tf32 tensor-core GEMM ---------------------
__global__ void gemm_tf32(const float* __restrict__ A, int P, long long GS, int RS,
                          int kchunks, const float* __restrict__ W, int ldw,
                          const float* __restrict__ bias, float* __restrict__ C, int ldc,
                          int mode, const float* __restrict__ nterm) {
  extern __shared__ float sm[];
  float* As = sm;               // 64 x 132
  float* Bs = sm + 64*132;      // 128 x 136
  const int m0 = blockIdx.x * 64;
  const int c0 = blockIdx.y * 128;
  const int tid = threadIdx.x;          // 256
  const int kq = tid >> 5, cq = tid & 31;
  const int lane = tid & 31, wid = tid >> 5;
  const int wm = wid & 1, wn = wid >> 1;
  const int g = lane >> 2, t4 = lane & 3;

  float acc[2][4][4];
  #pragma unroll
  for (int mt=0;mt<2;mt++)
    #pragma unroll
    for (int nt=0;nt<4;nt++)
      #pragma unroll
      for (int q=0;q<4;q++) acc[mt][nt][q] = 0.f;

  for (int kc = 0; kc < kchunks; ++kc) {
    if (kc) __syncthreads();
    #pragma unroll
    for (int it = 0; it < 8; ++it) {
      int r = kq + 8*it;
      int m = m0 + r;
      const float* ap = A + (long long)(m/P)*GS + (long long)(m%P)*RS + kc*128;
      float4 v = *(const float4*)(ap + 4*cq);
      float* dst = As + r*132 + 4*cq;
      dst[0]=tf32r(v.x); dst[1]=tf32r(v.y); dst[2]=tf32r(v.z); dst[3]=tf32r(v.w);
    }
    #pragma unroll
    for (int it = 0; it < 16; ++it) {
      int k = kq + 8*it;
      float4 v = *(const float4*)(W + (long long)(kc*128 + k)*ldw + c0 + 4*cq);
      float* dst = Bs + k*136 + 4*cq;
      dst[0]=tf32r(v.x); dst[1]=tf32r(v.y); dst[2]=tf32r(v.z); dst[3]=tf32r(v.w);
    }
    __syncthreads();
    #pragma unroll
    for (int k8 = 0; k8 < 16; ++k8) {
      const int kb = k8*8;
      uint32_t a[2][4];
      #pragma unroll
      for (int mt=0;mt<2;mt++) {
        int rb = wm*32 + mt*16 + g;
        a[mt][0] = __float_as_uint(As[rb*132     + kb + t4]);
        a[mt][1] = __float_as_uint(As[(rb+8)*132 + kb + t4]);
        a[mt][2] = __float_as_uint(As[rb*132     + kb + t4 + 4]);
        a[mt][3] = __float_as_uint(As[(rb+8)*132 + kb + t4 + 4]);
      }
      uint32_t b[4][2];
      #pragma unroll
      for (int nt=0;nt<4;nt++) {
        int nb = wn*32 + nt*8 + g;
        b[nt][0] = __float_as_uint(Bs[(kb+t4)*136   + nb]);
        b[nt][1] = __float_as_uint(Bs[(kb+t4+4)*136 + nb]);
      }
      #pragma unroll
      for (int mt=0;mt<2;mt++)
        #pragma unroll
        for (int nt=0;nt<4;nt++)
          mma8(acc[mt][nt], a[mt], b[nt]);
    }
  }
  #pragma unroll
  for (int mt=0;mt<2;mt++) {
    int row0 = m0 + wm*32 + mt*16 + g;
    #pragma unroll
    for (int nt=0;nt<4;nt++) {
      int col = c0 + wn*32 + nt*8 + 2*t4;
      #pragma unroll
      for (int h=0; h<2; ++h) {
        int row = row0 + 8*h;
        float v0 = acc[mt][nt][2*h+0], v1 = acc[mt][nt][2*h+1];
        if (mode == 0) { v0 += bias[col]; v1 += bias[col+1]; }
        else {
          const float* np = nterm + (long long)(row / T)*128;
          v0 = fmaxf(v0 + np[col],   0.f);
          v1 = fmaxf(v1 + np[col+1], 0.f);
        }
        float2 o = {v0, v1};
        *(float2*)(C + (long long)row*ldc + col) = o;
      }
    }
  }
}

// -------------------- GRU scan, tensor-core (32 rows/CTA) --------------------
__global__ __launch_bounds__(256, 1)
void gru_scan_mma(const float* __restrict__ Xp, const float* __restrict__ Bpack,
                  const float* __restrict__ brec, float* __restrict__ hs) {
  extern __shared__ float sm[];
  float* Bp = sm;                 // 49152
  float* Ab = sm + 49152;         // 2 * 32*132
  const int tid = threadIdx.x;    // 256
  const int w = tid >> 5, lane = tid & 31;
  const int g = lane >> 2, t4 = lane & 3;
  const int b0 = blockIdx.x * 32;
  #pragma unroll
  for (int it = 0; it < 48; ++it) {
    int o = (it*256 + tid)*4;
    *(float4*)(Bp + o) = *(const float4*)(Bpack + o);
  }
  for (int i = tid; i < 2*32*132; i += 256) Ab[i] = 0.f;
  float2 bz[2], brr[2], bh[2];
  #pragma unroll
  for (int nt=0; nt<2; ++nt) {
    int c = (2*w+nt)*8 + 2*t4;
    bz[nt]  = *(const float2*)(brec + c);
    brr[nt] = *(const float2*)(brec + 128 + c);
    bh[nt]  = *(const float2*)(brec + 256 + c);
  }
  float h[2][2][2][2];
  #pragma unroll
  for (int a1=0;a1<2;a1++)
    #pragma unroll
    for (int a2=0;a2<2;a2++)
      #pragma unroll
      for (int a3=0;a3<2;a3++) { h[a1][a2][a3][0]=0.f; h[a1][a2][a3][1]=0.f; }
  __syncthreads();

  for (int t = 0; t < T; ++t) {
    const float* Ar = Ab + (t & 1) * (32*132);
    float* Aw = Ab + ((t & 1) ^ 1) * (32*132);
    float2 xz[2][2][2], xr[2][2][2], xh[2][2][2];
    #pragma unroll
    for (int mt=0;mt<2;mt++)
      #pragma unroll
      for (int rh=0;rh<2;rh++) {
        long long base = ((long long)(b0 + mt*16 + rh*8 + g)*T + t)*N3 + 2*t4;
        #pragma unroll
        for (int nt=0;nt<2;nt++) {
          int c = (2*w+nt)*8;
          xz[mt][rh][nt] = *(const float2*)(Xp + base + c);
          xr[mt][rh][nt] = *(const float2*)(Xp + base + 128 + c);
          xh[mt][rh][nt] = *(const float2*)(Xp + base + 256 + c);
        }
      }
    float acc[2][6][4];
    #pragma unroll
    for (int mt=0;mt<2;mt++)
      #pragma unroll
      for (int j=0;j<6;j++)
        #pragma unroll
        for (int q=0;q<4;q++) acc[mt][j][q] = 0.f;
    #pragma unroll
    for (int k8=0;k8<16;++k8) {
      uint32_t a[2][4];
      #pragma unroll
      for (int mt=0;mt<2;mt++) {
        const float* ap = Ar + (mt*16 + g)*132 + k8*8 + t4;
        a[mt][0] = __float_as_uint(ap[0]);
        a[mt][1] = __float_as_uint(ap[8*132]);
        a[mt][2] = __float_as_uint(ap[4]);
        a[mt][3] = __float_as_uint(ap[8*132+4]);
      }
      float4 bv0 = *(const float4*)(Bp + ((k8*24 +      w)*32 + lane)*4);
      float4 bv1 = *(const float4*)(Bp + ((k8*24 +  8 + w)*32 + lane)*4);
      float4 bv2 = *(const float4*)(Bp + ((k8*24 + 16 + w)*32 + lane)*4);
      uint32_t bb[6][2];
      bb[0][0]=__float_as_uint(bv0.x); bb[0][1]=__float_as_uint(bv0.y);
      bb[1][0]=__float_as_uint(bv0.z); bb[1][1]=__float_as_uint(bv0.w);
      bb[2][0]=__float_as_uint(bv1.x); bb[2][1]=__float_as_uint(bv1.y);
      bb[3][0]=__float_as_uint(bv1.z); bb[3][1]=__float_as_uint(bv1.w);
      bb[4][0]=__float_as_uint(bv2.x); bb[4][1]=__float_as_uint(bv2.y);
      bb[5][0]=__float_as_uint(bv2.z); bb[5][1]=__float_as_uint(bv2.w);
      #pragma unroll
      for (int mt=0;mt<2;mt++)
        #pragma unroll
        for (int j=0;j<6;j++)
          mma8(acc[mt][j], a[mt], bb[j]);
    }
    #pragma unroll
    for (int mt=0;mt<2;mt++)
      #pragma unroll
      for (int rh=0;rh<2;rh++) {
        int row = mt*16 + rh*8 + g;
        long long grow = ((long long)(b0+row)*T + t)*128;
        #pragma unroll
        for (int nt=0;nt<2;nt++) {
          int c = (2*w+nt)*8 + 2*t4;
          float hn0, hn1;
          {
            float z  = sig_(xz[mt][rh][nt].x + acc[mt][nt][rh*2]     + bz[nt].x);
            float r  = sig_(xr[mt][rh][nt].x + acc[mt][2+nt][rh*2]   + brr[nt].x);
            float hc = tanh_(xh[mt][rh][nt].x + r*(acc[mt][4+nt][rh*2] + bh[nt].x));
            float ho = h[mt][rh][nt][0];
            hn0 = z*ho + (1.f - z)*hc;
            h[mt][rh][nt][0] = hn0;
          }
          {
            float z  = sig_(xz[mt][rh][nt].y + acc[mt][nt][rh*2+1]     + bz[nt].y);
            float r  = sig_(xr[mt][rh][nt].y + acc[mt][2+nt][rh*2+1]   + brr[nt].y);
            float hc = tanh_(xh[mt][rh][nt].y + r*(acc[mt][4+nt][rh*2+1] + bh[nt].y));
            float ho = h[mt][rh][nt][1];
            hn1 = z*ho + (1.f - z)*hc;
            h[mt][rh][nt][1] = hn1;
          }
          float2 o = {hn0, hn1};
          *(float2*)(hs + grow + c) = o;
          float2 rt = {tf32r(hn0), tf32r(hn1)};
          *(float2*)(Aw + row*132 + c) = rt;
        }
      }
    __syncthreads();
  }
}

// -------------------- AUGRU scan, tensor-core --------------------
__global__ __launch_bounds__(256, 1)
void augru_scan_mma(const float* __restrict__ X3, const float* __restrict__ Bpack) {
  extern __shared__ float sm[];
  float* Bp = sm;
  float* Ab = sm + 49152;
  const int tid = threadIdx.x;
  const int w = tid >> 5, lane = tid & 31;
  const int g = lane >> 2, t4 = lane & 3;
  const int b0 = blockIdx.x * 32;
  #pragma unroll
  for (int it = 0; it < 48; ++it) {
    int o = (it*256 + tid)*4;
    *(float4*)(Bp + o) = *(const float4*)(Bpack + o);
  }
  for (int i = tid; i < 2*32*132; i += 256) Ab[i] = 0.f;
  float h[2][2][2][2];
  #pragma unroll
  for (int a1=0;a1<2;a1++)
    #pragma unroll
    for (int a2=0;a2<2;a2++)
      #pragma unroll
      for (int a3=0;a3<2;a3++) { h[a1][a2][a3][0]=0.f; h[a1][a2][a3][1]=0.f; }
  __syncthreads();

  for (int t = 0; t < T; ++t) {
    const float* Ar = Ab + (t & 1) * (32*132);
    float* Aw = Ab + ((t & 1) ^ 1) * (32*132);
    float2 xu[2][2][2], xr[2][2][2], xc[2][2][2];
    float at[2][2];
    #pragma unroll
    for (int mt=0;mt<2;mt++)
      #pragma unroll
      for (int rh=0;rh<2;rh++) {
        long long rowg = (long long)(b0 + mt*16 + rh*8 + g)*T + t;
        at[mt][rh] = g_ats[rowg];
        long long base = rowg*N3 + 2*t4;
        #pragma unroll
        for (int nt=0;nt<2;nt++) {
          int c = (2*w+nt)*8;
          xu[mt][rh][nt] = *(const float2*)(X3 + base + c);
          xr[mt][rh][nt] = *(const float2*)(X3 + base + 128 + c);
          xc[mt][rh][nt] = *(const float2*)(X3 + base + 256 + c);
        }
      }
    float acc[2][6][4];
    #pragma unroll
    for (int mt=0;mt<2;mt++)
      #pragma unroll
      for (int j=0;j<6;j++)
        #pragma unroll
        for (int q=0;q<4;q++) acc[mt][j][q] = 0.f;
    #pragma unroll
    for (int k8=0;k8<16;++k8) {
      uint32_t a[2][4];
      #pragma unroll
      for (int mt=0;mt<2;mt++) {
        const float* ap = Ar + (mt*16 + g)*132 + k8*8 + t4;
        a[mt][0] = __float_as_uint(ap[0]);
        a[mt][1] = __float_as_uint(ap[8*132]);
        a[mt][2] = __float_as_uint(ap[4]);
        a[mt][3] = __float_as_uint(ap[8*132+4]);
      }
      float4 bv0 = *(const float4*)(Bp + ((k8*24 +      w)*32 + lane)*4);
      float4 bv1 = *(const float4*)(Bp + ((k8*24 +  8 + w)*32 + lane)*4);
      float4 bv2 = *(const float4*)(Bp + ((k8*24 + 16 + w)*32 + lane)*4);
      uint32_t bb[6][2];
      bb[0][0]=__float_as_uint(bv0.x); bb[0][1]=__float_as_uint(bv0.y);
      bb[1][0]=__float_as_uint(bv0.z); bb[1][1]=__float_as_uint(bv0.w);
      bb[2][0]=__float_as_uint(bv1.x); bb[2][1]=__float_as_uint(bv1.y);
      bb[3][0]=__float_as_uint(bv1.z); bb[3][1]=__float_as_uint(bv1.w);
      bb[4][0]=__float_as_uint(bv2.x); bb[4][1]=__float_as_uint(bv2.y);
      bb[5][0]=__float_as_uint(bv2.z); bb[5][1]=__float_as_uint(bv2.w);
      #pragma unroll
      for (int mt=0;mt<2;mt++)
        #pragma unroll
        for (int j=0;j<6;j++)
          mma8(acc[mt][j], a[mt], bb[j]);
    }
    #pragma unroll
    for (int mt=0;mt<2;mt++)
      #pragma unroll
      for (int rh=0;rh<2;rh++) {
        int row = mt*16 + rh*8 + g;
        float atv = at[mt][rh];
        #pragma unroll
        for (int nt=0;nt<2;nt++) {
          int c = (2*w+nt)*8 + 2*t4;
          float hn0, hn1;
          {
            float u  = sig_(xu[mt][rh][nt].x + acc[mt][nt][rh*2]);
            float r  = sig_(xr[mt][rh][nt].x + acc[mt][2+nt][rh*2]);
            float cc = tanh_(xc[mt][rh][nt].x + r*acc[mt][4+nt][rh*2]);
            float uu = atv*u;
            float ho = h[mt][rh][nt][0];
            hn0 = (1.f - uu)*ho + uu*cc;
            h[mt][rh][nt][0] = hn0;
          }
          {
            float u  = sig_(xu[mt][rh][nt].y + acc[mt][nt][rh*2+1]);
            float r  = sig_(xr[mt][rh][nt].y + acc[mt][2+nt][rh*2+1]);
            float cc = tanh_(xc[mt][rh][nt].y + r*acc[mt][4+nt][rh*2+1]);
            float uu = atv*u;
            float ho = h[mt][rh][nt][1];
            hn1 = (1.f - uu)*ho + uu*cc;
            h[mt][rh][nt][1] = hn1;
          }
          float2 rt = {tf32r(hn0), tf32r(hn1)};
          *(float2*)(Aw + row*132 + c) = rt;
        }
      }
    __syncthreads();
  }
  #pragma unroll
  for (int mt=0;mt<2;mt++)
    #pragma unroll
    for (int rh=0;rh<2;rh++) {
      int row = mt*16 + rh*8 + g;
      #pragma unroll
      for (int nt=0;nt<2;nt++) {
        int c = (2*w+nt)*8 + 2*t4;
        float2 o = {h[mt][rh][nt][0], h[mt][rh][nt][1]};
        *(float2*)(g_hfin + (long long)(b0+row)*128 + c) = o;
      }
    }
}

// ------------------------------ Zcat = [hs | hs*news] ------------------------------
__global__ void zcat_kernel(const float* __restrict__ hs, const float* __restrict__ inputs,
                            float* __restrict__ Z) {
  long long idx = (long long)blockIdx.x*256 + threadIdx.x;
  long long row = idx >> 5;
  int q = (int)(idx & 31);
  int b = (int)(row / T);
  float4 h  = *(const float4*)(hs + row*128 + 4*q);
  float4 nw = *(const float4*)(inputs + ((long long)b*(T+1) + T)*128 + 4*q);
  *(float4*)(Z + row*256 + 4*q) = h;
  float4 p; p.x=h.x*nw.x; p.y=h.y*nw.y; p.z=h.z*nw.z; p.w=h.w*nw.w;
  *(float4*)(Z + row*256 + 128 + 4*q) = p;
}

// ------------------------------ attention layer2 + score ------------------------------
__global__ void att2_kernel(const float* __restrict__ a1, const float* __restrict__ W2,
                            const float* __restrict__ b2, const float* __restrict__ W3,
                            const float* __restrict__ b3) {
  extern __shared__ float sm[];
  float* a1s = sm;            // 64 x 132
  float* a2s = sm + 64*132;   // 64 x 68
  float* W3s = a2s + 64*68;   // 64
  const int tid = threadIdx.x;   // 256
  const long long m0 = (long long)blockIdx.x * 64;
  #pragma unroll
  for (int it = 0; it < 8; ++it) {
    int idx = it*256 + tid;
    int r = idx >> 5, c4 = idx & 31;
    float4 v = *(const float4*)(a1 + (m0 + r)*128 + 4*c4);
    *(float4*)(a1s + r*132 + 4*c4) = v;
  }
  if (tid < 64) W3s[tid] = W3[tid];
  const int c = tid >> 2, rg = tid & 3;
  float w[32];
  #pragma unroll
  for (int kk=0;kk<32;kk++) w[kk] = W2[(rg*32 + kk)*64 + c];
  const float b2c = b2[c];
  __syncthreads();
  for (int r = 0; r < 64; ++r) {
    const float4* ap = (const float4*)(a1s + r*132 + rg*32);
    float dot = 0.f;
    #pragma unroll
    for (int q=0;q<8;q++) {
      float4 v = ap[q];
      dot = fmaf(v.x, w[4*q+0], dot);
      dot = fmaf(v.y, w[4*q+1], dot);
      dot = fmaf(v.z, w[4*q+2], dot);
      dot = fmaf(v.w, w[4*q+3], dot);
    }
    dot += __shfl_xor_sync(0xffffffffu, dot, 1);
    dot += __shfl_xor_sync(0xffffffffu, dot, 2);
    if (rg == 0) a2s[r*68 + c] = fmaxf(dot + b2c, 0.f);
  }
  __syncthreads();
  if (tid < 64) {
    float accv = b3[0];
    #pragma unroll 8
    for (int cc=0; cc<64; ++cc) accv = fmaf(a2s[tid*68 + cc], W3s[cc], accv);
    g_ats[m0 + tid] = sigf(accv);
  }
}

// ------------------------------ head ------------------------------
__global__ void head_kernel(const float* __restrict__ inputs,
                            const float* __restrict__ gamma, const float* __restrict__ beta,
                            const float* __restrict__ mean,  const float* __restrict__ var,
                            const float* __restrict__ W1, const float* __restrict__ bb1,
                            const float* __restrict__ W2, const float* __restrict__ bb2,
                            const float* __restrict__ fW, const float* __restrict__ fb,
                            float* __restrict__ out) {
  extern __shared__ float sm[];
  float* xs  = sm;          // 32*256
  float* y1s = xs + 8192;   // 32*256
  float* y2s = y1s + 8192;  // 32*128
  const int tid = threadIdx.x;   // 256
  const int b0 = blockIdx.x * 32;
  for (int r = 0; r < 32; ++r) {
    int k = tid;
    int bb = b0 + r;
    float v = (k < 128) ? g_hfin[bb*128 + k]
                        : inputs[((long long)bb*(T+1) + T)*128 + (k - 128)];
    float nv = (v - mean[k]) * rsqrtf(var[k] + BN_EPS) * gamma[k] + beta[k];
    xs[r*256 + k] = nv;
  }
  __syncthreads();
  {
    float acc[32];
    #pragma unroll
    for (int r=0;r<32;r++) acc[r] = bb1[tid];
    for (int k=0;k<256;++k) {
      float w = W1[k*256 + tid];
      #pragma unroll
      for (int r=0;r<32;r++) acc[r] = fmaf(xs[r*256+k], w, acc[r]);
    }
    #pragma unroll
    for (int r=0;r<32;r++) {
      float v = acc[r];
      y1s[r*256 + tid] = v >= 0.f ? v : LEAKY*v;
    }
  }
  __syncthreads();
  if (tid < 128) {
    float acc[32];
    #pragma unroll
    for (int r=0;r<32;r++) acc[r] = bb2[tid];
    for (int k=0;k<256;++k) {
      float w = W2[k*128 + tid];
      #pragma unroll
      for (int r=0;r<32;r++) acc[r] = fmaf(y1s[r*256+k], w, acc[r]);
    }
    #pragma unroll
    for (int r=0;r<32;r++) {
      float v = acc[r];
      y2s[r*128 + tid] = v >= 0.f ? v : LEAKY*v;
    }
  }
  __syncthreads();
  if (tid < 32) {
    float acc = fb[0];
    for (int k=0;k<128;++k) acc = fmaf(y2s[tid*128+k], fW[k], acc);
    out[b0 + tid] = sigf(acc);
  }
}

// ------------------------------ launch ------------------------------
extern "C" void kernel_launch(void* const* d_in, const int* in_sizes, int n_in,
                              void* d_out, int out_size) {
  (void)in_sizes; (void)n_in; (void)out_size;
  const float* inputs  = (const float*)d_in[0];
  const float* gru_W   = (const float*)d_in[1];
  const float* gru_U   = (const float*)d_in[2];
  const float* gru_b   = (const float*)d_in[3];
  const float* att_W1  = (const float*)d_in[4];
  const float* att_b1  = (const float*)d_in[5];
  const float* att_W2  = (const float*)d_in[6];
  const float* att_b2  = (const float*)d_in[7];
  const float* att_W3  = (const float*)d_in[8];
  const float* att_b3  = (const float*)d_in[9];
  const float* au_Wu   = (const float*)d_in[10];
  const float* au_bu   = (const float*)d_in[11];
  const float* au_Uu   = (const float*)d_in[12];
  const float* au_Wr   = (const float*)d_in[13];
  const float* au_br   = (const float*)d_in[14];
  const float* au_Ur   = (const float*)d_in[15];
  const float* au_Wc   = (const float*)d_in[16];
  const float* au_bc   = (const float*)d_in[17];
  const float* au_Uc   = (const float*)d_in[18];
  const float* bn_gamma= (const float*)d_in[19];
  const float* bn_beta = (const float*)d_in[20];
  const float* bn_mean = (const float*)d_in[21];
  const float* bn_var  = (const float*)d_in[22];
  const float* d_W1    = (const float*)d_in[23];
  const float* d_b1    = (const float*)d_in[24];
  const float* d_W2    = (const float*)d_in[25];
  const float* d_b2    = (const float*)d_in[26];
  const float* f_W     = (const float*)d_in[27];
  const float* f_b     = (const float*)d_in[28];
  float* out = (float*)d_out;

  const size_t sm_gemm = (64*132 + 128*136)*sizeof(float);
  const size_t sm_scan = (49152 + 2*32*132)*sizeof(float);   // 230400 B
  const size_t sm_att2 = (64*132 + 64*68 + 64)*sizeof(float);
  const size_t sm_head = (8192*2 + 4096)*sizeof(float);
  cudaFuncSetAttribute(gemm_tf32,      cudaFuncAttributeMaxDynamicSharedMemorySize, (int)sm_gemm);
  cudaFuncSetAttribute(gru_scan_mma,   cudaFuncAttributeMaxDynamicSharedMemorySize, (int)sm_scan);
  cudaFuncSetAttribute(augru_scan_mma, cudaFuncAttributeMaxDynamicSharedMemorySize, (int)sm_scan);
  cudaFuncSetAttribute(att2_kernel,    cudaFuncAttributeMaxDynamicSharedMemorySize, (int)sm_att2);
  cudaFuncSetAttribute(head_kernel,    cudaFuncAttributeMaxDynamicSharedMemorySize, (int)sm_head);

  float *p_Xp, *p_hs, *p_X3, *p_newsterm, *p_Wau, *p_bau, *p_Wcat, *p_W1bc, *p_Uau;
  float *p_Upg, *p_Upa;
  cudaGetSymbolAddress((void**)&p_Xp,       g_Xp);
  cudaGetSymbolAddress((void**)&p_hs,       g_hs);
  cudaGetSymbolAddress((void**)&p_X3,       g_X3);
  cudaGetSymbolAddress((void**)&p_newsterm, g_newsterm);
  cudaGetSymbolAddress((void**)&p_Wau,      g_Wau);
  cudaGetSymbolAddress((void**)&p_bau,      g_bau);
  cudaGetSymbolAddress((void**)&p_Wcat,     g_Wcat);
  cudaGetSymbolAddress((void**)&p_W1bc,     g_W1bc);
  cudaGetSymbolAddress((void**)&p_Uau,      g_Uau);
  cudaGetSymbolAddress((void**)&p_Upg,      g_Upack_gru);
  cudaGetSymbolAddress((void**)&p_Upa,      g_Upack_au);

  // 1) pack AU weights + attention folded weights
  prep_kernel<<<192, 256>>>(au_Wu, au_bu, au_Wr, au_br, au_Wc, au_bc,
                            au_Uu, au_Ur, au_Uc, att_W1);
  // 1b) fragment-pack recurrent matrices
  pack_frag_kernel<<<192, 256>>>(gru_U, p_Upg);
  pack_frag_kernel<<<192, 256>>>(p_Uau, p_Upa);
  // 2) Xp = hist @ gru_W + gru_b[0]
  gemm_tf32<<<dim3(BT/64, 3), 256, sm_gemm>>>(inputs, T, (long long)(T+1)*128, 128, 1,
                                              gru_W, 384, gru_b, p_Xp, 384, 0, nullptr);
  // 3) newsterm = news @ (W1B+W1C) + b1
  gemm_tf32<<<dim3(B/64, 1), 256, sm_gemm>>>(inputs + (long long)T*128, 1, (long long)(T+1)*128, 128, 1,
                                             p_W1bc, 128, att_b1, p_newsterm, 128, 0, nullptr);
  // 4) GRU recurrence -> hs (tensor-core scan)
  gru_scan_mma<<<B/32, 256, sm_scan>>>(p_Xp, p_Upg, gru_b + 384, p_hs);
  // 5) Zcat = [hs | hs*news]
  zcat_kernel<<<BT*32/256, 256>>>(p_hs, inputs, p_Xp);
  // 6) a1 = relu(Zcat @ Wcat + newsterm)
  gemm_tf32<<<dim3(BT/64, 1), 256, sm_gemm>>>(p_Xp, 1<<30, 0LL, 256, 2,
                                              p_Wcat, 128, nullptr, p_X3, 128, 1, p_newsterm);
  // 7) attention layer2 + score -> g_ats
  att2_kernel<<<BT/64, 256, sm_att2>>>(p_X3, att_W2, att_b2, att_W3, att_b3);
  // 8) X3 = hs @ [Wu|Wr|Wc] + [bu|br|bc]
  gemm_tf32<<<dim3(BT/64, 3), 256, sm_gemm>>>(p_hs, 1<<30, 0LL, 128, 1,
                                              p_Wau, 384, p_bau, p_X3, 384, 0, nullptr);
  // 9) AUGRU recurrence -> hfin (tensor-core scan)
  augru_scan_mma<<<B/32, 256, sm_scan>>>(p_X3, p_Upa);
  // 10) BN + dense head -> out
  head_kernel<<<B/32, 256, sm_head>>>(inputs, bn_gamma, bn_beta, bn_mean, bn_var,
                                      d_W1, d_b1, d_W2, d_b2, f_W, f_b, out);
}

// round 5
// speedup vs baseline: 3.4772x; 1.4737x over previous
#include <cuda_runtime.h>
#include <math.h>
#include <stdint.h>

#define B  4096
#define T  50
#define U  128
#define N3 384
#define BT (B*T)
#define BN_EPS 1e-3f
#define LEAKY  3e-4f

// ------------ scratch (device globals; no allocation allowed) ------------
__device__ float g_Xp[BT*N3];        // GRU input projection
__device__ float g_hs[BT*U];         // GRU hidden states
__device__ float g_X3[BT*N3];        // AUGRU input projections
__device__ float g_ats[BT];          // attention scores
__device__ float g_hfin[B*U];        // AUGRU final state
__device__ float g_newsterm[B*U];    // news@(W1B+W1C)+b1
__device__ float g_Wau[U*N3];        // packed input  [Wu|Wr|Wc]
__device__ float g_Uau[U*N3];        // packed recur  [Uu|Ur|Uc]
__device__ float g_bau[N3];          // packed [bu|br|bc]
__device__ float g_Wcat[2*U*U];      // [W1A-W1B ; W1D]  (256 x 128)
__device__ float g_W1bc[U*U];        // W1B + W1C
__device__ float g_Upack_gru[128*N3];// fragment-ordered gru_U
__device__ float g_Upack_au[128*N3]; // fragment-ordered [Uu|Ur|Uc]
__device__ float g_Wp_gruW[128*N3];  // fragment-ordered gru_W
__device__ float g_Wp_au[128*N3];    // fragment-ordered [Wu|Wr|Wc]
__device__ float g_Wp_1bc[128*128];  // fragment-ordered W1B+W1C
__device__ float g_Wp_cat[256*128];  // fragment-ordered Wcat (K=256)
__device__ float g_Wp_att2[128*64];  // fragment-ordered att_W2

__device__ __forceinline__ float sigf(float x){ return 1.f/(1.f+expf(-x)); }
__device__ __forceinline__ float sig_(float x){ return __fdividef(1.f, 1.f + __expf(-x)); }
__device__ __forceinline__ float tanh_(float x){ return 1.f - 2.f*__fdividef(1.f, 1.f + __expf(2.f*x)); }
__device__ __forceinline__ float tf32r(float f){
  uint32_t r; asm("cvt.rna.tf32.f32 %0, %1;" : "=r"(r) : "f"(f));
  return __uint_as_float(r);
}
__device__ __forceinline__ void mma8(float* d, const uint32_t* a, const uint32_t* b){
  asm volatile("mma.sync.aligned.m16n8k8.row.col.f32.tf32.tf32.f32 "
               "{%0,%1,%2,%3}, {%4,%5,%6,%7}, {%8,%9}, {%0,%1,%2,%3};"
               : "+f"(d[0]), "+f"(d[1]), "+f"(d[2]), "+f"(d[3])
               : "r"(a[0]), "r"(a[1]), "r"(a[2]), "r"(a[3]), "r"(b[0]), "r"(b[1]));
}

// ------------------------------- prep -------------------------------
__global__ void prep_kernel(const float* __restrict__ Wu, const float* __restrict__ bu,
                            const float* __restrict__ Wr, const float* __restrict__ br,
                            const float* __restrict__ Wc, const float* __restrict__ bc,
                            const float* __restrict__ Uu, const float* __restrict__ Ur,
                            const float* __restrict__ Uc,
                            const float* __restrict__ attW1) {
  int id = blockIdx.x*blockDim.x + threadIdx.x;
  if (id < U*N3) {
    int k = id / N3, c = id % N3;
    float w, u;
    if (c < 128)      { w = Wu[k*128 + c];       u = Uu[k*128 + c]; }
    else if (c < 256) { w = Wr[k*128 + (c-128)]; u = Ur[k*128 + (c-128)]; }
    else              { w = Wc[k*128 + (c-256)]; u = Uc[k*128 + (c-256)]; }
    g_Wau[id] = w;
    g_Uau[id] = u;
  }
  if (id < N3)
    g_bau[id] = (id < 128) ? bu[id] : (id < 256 ? br[id-128] : bc[id-256]);
  if (id < 2*U*U) {
    int k = id / 128, c = id % 128;
    float v;
    if (k < 128) v = attW1[k*128 + c] - attW1[U*U + k*128 + c];     // W1A - W1B
    else         v = attW1[3*U*U + (k-128)*128 + c];                // W1D
    g_Wcat[id] = v;
  }
  if (id < U*U)
    g_W1bc[id] = attW1[U*U + id] + attW1[2*U*U + id];
}

// --------------- pack weights fragment-ordered (tf32) ---------------
// P[((k8*Ntp + tp)*32 + lane)*4 + q]: tile=2*tp+(q>>1), reg=q&1,
//   k = k8*8 + (lane&3) + 4*reg,  n = tile*8 + (lane>>2), value = Um[k*N + n]
__global__ void pack_frag_n(const float* __restrict__ Um, float* __restrict__ P,
                            int N, int total) {
  int idx = blockIdx.x*256 + threadIdx.x;
  if (idx >= total) return;
  int q = idx & 3, lane = (idx >> 2) & 31;
  int Ntp = N >> 4;
  int tp = (idx >> 7) % Ntp, k8 = (idx >> 7) / Ntp;
  int tile = 2*tp + (q >> 1), r = q & 1;
  int k = k8*8 + (lane & 3) + 4*r;
  int n = tile*8 + (lane >> 2);
  P[idx] = tf32r(Um[k*N + n]);
}

// --------------------- tf32 GEMM, packed-B, K=128 ---------------------
__global__ void gemm_v2(const float* __restrict__ A, int P, long long GS, int RS,
                        const float* __restrict__ Bpk, int Ntp,
                        const float* __restrict__ bias, float* __restrict__ C, int ldc) {
  extern __shared__ float sm[];
  float* As = sm;               // 64 x 132
  float* Bp = sm + 64*132;      // 16384 floats
  const int m0 = blockIdx.x * 64;
  const int c0 = blockIdx.y * 128;
  const int tp0 = blockIdx.y * 8;
  const int tid = threadIdx.x;          // 256
  const int kq = tid >> 5, cq = tid & 31;
  const int lane = tid & 31, wid = tid >> 5;
  const int wm = wid & 1, wn = wid >> 1;
  const int g = lane >> 2, t4 = lane & 3;

  #pragma unroll
  for (int it = 0; it < 8; ++it) {
    int r = kq + 8*it;
    int m = m0 + r;
    const float* ap = A + (long long)(m/P)*GS + (long long)(m%P)*RS;
    float4 v = *(const float4*)(ap + 4*cq);
    float* dst = As + r*132 + 4*cq;
    dst[0]=tf32r(v.x); dst[1]=tf32r(v.y); dst[2]=tf32r(v.z); dst[3]=tf32r(v.w);
  }
  {
    const float4* src = (const float4*)Bpk;
    float4* dst = (float4*)Bp;
    #pragma unroll
    for (int it = 0; it < 16; ++it) {
      int f = it*256 + tid;
      int k8 = f >> 8, rem = f & 255;
      dst[f] = src[((long long)k8*Ntp + tp0)*32 + rem];
    }
  }
  __syncthreads();

  float acc[2][4][4];
  #pragma unroll
  for (int mt=0;mt<2;mt++)
    #pragma unroll
    for (int nt=0;nt<4;nt++)
      #pragma unroll
      for (int q=0;q<4;q++) acc[mt][nt][q] = 0.f;

  const float4* bp4 = (const float4*)Bp;
  #pragma unroll
  for (int k8 = 0; k8 < 16; ++k8) {
    uint32_t a[2][4];
    #pragma unroll
    for (int mt=0;mt<2;mt++) {
      const float* ap = As + (wm*32 + mt*16 + g)*132 + k8*8 + t4;
      a[mt][0] = __float_as_uint(ap[0]);
      a[mt][1] = __float_as_uint(ap[8*132]);
      a[mt][2] = __float_as_uint(ap[4]);
      a[mt][3] = __float_as_uint(ap[8*132+4]);
    }
    float4 b40 = bp4[(k8*8 + wn*2    )*32 + lane];
    float4 b41 = bp4[(k8*8 + wn*2 + 1)*32 + lane];
    uint32_t bb[4][2];
    bb[0][0]=__float_as_uint(b40.x); bb[0][1]=__float_as_uint(b40.y);
    bb[1][0]=__float_as_uint(b40.z); bb[1][1]=__float_as_uint(b40.w);
    bb[2][0]=__float_as_uint(b41.x); bb[2][1]=__float_as_uint(b41.y);
    bb[3][0]=__float_as_uint(b41.z); bb[3][1]=__float_as_uint(b41.w);
    #pragma unroll
    for (int mt=0;mt<2;mt++)
      #pragma unroll
      for (int nt=0;nt<4;nt++)
        mma8(acc[mt][nt], a[mt], bb[nt]);
  }
  #pragma unroll
  for (int mt=0;mt<2;mt++) {
    int row0 = m0 + wm*32 + mt*16 + g;
    #pragma unroll
    for (int nt=0;nt<4;nt++) {
      int col = c0 + wn*32 + nt*8 + 2*t4;
      #pragma unroll
      for (int h=0; h<2; ++h) {
        int row = row0 + 8*h;
        float2 o = {acc[mt][nt][2*h+0] + bias[col], acc[mt][nt][2*h+1] + bias[col+1]};
        *(float2*)(C + (long long)row*ldc + col) = o;
      }
    }
  }
}

// -------------------- GRU scan, tensor-core (32 rows/CTA) --------------------
__global__ __launch_bounds__(256, 1)
void gru_scan_mma(const float* __restrict__ Xp, const float* __restrict__ Bpack,
                  const float* __restrict__ brec, float* __restrict__ hs) {
  extern __shared__ float sm[];
  float* Bp = sm;                 // 49152
  float* Ab = sm + 49152;         // 2 * 32*132
  const int tid = threadIdx.x;    // 256
  const int w = tid >> 5, lane = tid & 31;
  const int g = lane >> 2, t4 = lane & 3;
  const int b0 = blockIdx.x * 32;
  #pragma unroll
  for (int it = 0; it < 48; ++it) {
    int o = (it*256 + tid)*4;
    *(float4*)(Bp + o) = *(const float4*)(Bpack + o);
  }
  for (int i = tid; i < 2*32*132; i += 256) Ab[i] = 0.f;
  float2 bz[2], brr[2], bh[2];
  #pragma unroll
  for (int nt=0; nt<2; ++nt) {
    int c = (2*w+nt)*8 + 2*t4;
    bz[nt]  = *(const float2*)(brec + c);
    brr[nt] = *(const float2*)(brec + 128 + c);
    bh[nt]  = *(const float2*)(brec + 256 + c);
  }
  float h[2][2][2][2];
  #pragma unroll
  for (int a1=0;a1<2;a1++)
    #pragma unroll
    for (int a2=0;a2<2;a2++)
      #pragma unroll
      for (int a3=0;a3<2;a3++) { h[a1][a2][a3][0]=0.f; h[a1][a2][a3][1]=0.f; }
  __syncthreads();

  for (int t = 0; t < T; ++t) {
    const float* Ar = Ab + (t & 1) * (32*132);
    float* Aw = Ab + ((t & 1) ^ 1) * (32*132);
    float2 xz[2][2][2], xr[2][2][2], xh[2][2][2];
    #pragma unroll
    for (int mt=0;mt<2;mt++)
      #pragma unroll
      for (int rh=0;rh<2;rh++) {
        long long base = ((long long)(b0 + mt*16 + rh*8 + g)*T + t)*N3 + 2*t4;
        #pragma unroll
        for (int nt=0;nt<2;nt++) {
          int c = (2*w+nt)*8;
          xz[mt][rh][nt] = *(const float2*)(Xp + base + c);
          xr[mt][rh][nt] = *(const float2*)(Xp + base + 128 + c);
          xh[mt][rh][nt] = *(const float2*)(Xp + base + 256 + c);
        }
      }
    float acc[2][6][4];
    #pragma unroll
    for (int mt=0;mt<2;mt++)
      #pragma unroll
      for (int j=0;j<6;j++)
        #pragma unroll
        for (int q=0;q<4;q++) acc[mt][j][q] = 0.f;
    #pragma unroll
    for (int k8=0;k8<16;++k8) {
      uint32_t a[2][4];
      #pragma unroll
      for (int mt=0;mt<2;mt++) {
        const float* ap = Ar + (mt*16 + g)*132 + k8*8 + t4;
        a[mt][0] = __float_as_uint(ap[0]);
        a[mt][1] = __float_as_uint(ap[8*132]);
        a[mt][2] = __float_as_uint(ap[4]);
        a[mt][3] = __float_as_uint(ap[8*132+4]);
      }
      float4 bv0 = *(const float4*)(Bp + ((k8*24 +      w)*32 + lane)*4);
      float4 bv1 = *(const float4*)(Bp + ((k8*24 +  8 + w)*32 + lane)*4);
      float4 bv2 = *(const float4*)(Bp + ((k8*24 + 16 + w)*32 + lane)*4);
      uint32_t bb[6][2];
      bb[0][0]=__float_as_uint(bv0.x); bb[0][1]=__float_as_uint(bv0.y);
      bb[1][0]=__float_as_uint(bv0.z); bb[1][1]=__float_as_uint(bv0.w);
      bb[2][0]=__float_as_uint(bv1.x); bb[2][1]=__float_as_uint(bv1.y);
      bb[3][0]=__float_as_uint(bv1.z); bb[3][1]=__float_as_uint(bv1.w);
      bb[4][0]=__float_as_uint(bv2.x); bb[4][1]=__float_as_uint(bv2.y);
      bb[5][0]=__float_as_uint(bv2.z); bb[5][1]=__float_as_uint(bv2.w);
      #pragma unroll
      for (int mt=0;mt<2;mt++)
        #pragma unroll
        for (int j=0;j<6;j++)
          mma8(acc[mt][j], a[mt], bb[j]);
    }
    #pragma unroll
    for (int mt=0;mt<2;mt++)
      #pragma unroll
      for (int rh=0;rh<2;rh++) {
        int row = mt*16 + rh*8 + g;
        long long grow = ((long long)(b0+row)*T + t)*128;
        #pragma unroll
        for (int nt=0;nt<2;nt++) {
          int c = (2*w+nt)*8 + 2*t4;
          float hn0, hn1;
          {
            float z  = sig_(xz[mt][rh][nt].x + acc[mt][nt][rh*2]     + bz[nt].x);
            float r  = sig_(xr[mt][rh][nt].x + acc[mt][2+nt][rh*2]   + brr[nt].x);
            float hc = tanh_(xh[mt][rh][nt].x + r*(acc[mt][4+nt][rh*2] + bh[nt].x));
            float ho = h[mt][rh][nt][0];
            hn0 = z*ho + (1.f - z)*hc;
            h[mt][rh][nt][0] = hn0;
          }
          {
            float z  = sig_(xz[mt][rh][nt].y + acc[mt][nt][rh*2+1]     + bz[nt].y);
            float r  = sig_(xr[mt][rh][nt].y + acc[mt][2+nt][rh*2+1]   + brr[nt].y);
            float hc = tanh_(xh[mt][rh][nt].y + r*(acc[mt][4+nt][rh*2+1] + bh[nt].y));
            float ho = h[mt][rh][nt][1];
            hn1 = z*ho + (1.f - z)*hc;
            h[mt][rh][nt][1] = hn1;
          }
          float2 o = {hn0, hn1};
          *(float2*)(hs + grow + c) = o;
          float2 rt = {tf32r(hn0), tf32r(hn1)};
          *(float2*)(Aw + row*132 + c) = rt;
        }
      }
    __syncthreads();
  }
}

// -------------------- AUGRU scan, tensor-core --------------------
__global__ __launch_bounds__(256, 1)
void augru_scan_mma(const float* __restrict__ X3, const float* __restrict__ Bpack) {
  extern __shared__ float sm[];
  float* Bp = sm;
  float* Ab = sm + 49152;
  const int tid = threadIdx.x;
  const int w = tid >> 5, lane = tid & 31;
  const int g = lane >> 2, t4 = lane & 3;
  const int b0 = blockIdx.x * 32;
  #pragma unroll
  for (int it = 0; it < 48; ++it) {
    int o = (it*256 + tid)*4;
    *(float4*)(Bp + o) = *(const float4*)(Bpack + o);
  }
  for (int i = tid; i < 2*32*132; i += 256) Ab[i] = 0.f;
  float h[2][2][2][2];
  #pragma unroll
  for (int a1=0;a1<2;a1++)
    #pragma unroll
    for (int a2=0;a2<2;a2++)
      #pragma unroll
      for (int a3=0;a3<2;a3++) { h[a1][a2][a3][0]=0.f; h[a1][a2][a3][1]=0.f; }
  __syncthreads();

  for (int t = 0; t < T; ++t) {
    const float* Ar = Ab + (t & 1) * (32*132);
    float* Aw = Ab + ((t & 1) ^ 1) * (32*132);
    float2 xu[2][2][2], xr[2][2][2], xc[2][2][2];
    float at[2][2];
    #pragma unroll
    for (int mt=0;mt<2;mt++)
      #pragma unroll
      for (int rh=0;rh<2;rh++) {
        long long rowg = (long long)(b0 + mt*16 + rh*8 + g)*T + t;
        at[mt][rh] = g_ats[rowg];
        long long base = rowg*N3 + 2*t4;
        #pragma unroll
        for (int nt=0;nt<2;nt++) {
          int c = (2*w+nt)*8;
          xu[mt][rh][nt] = *(const float2*)(X3 + base + c);
          xr[mt][rh][nt] = *(const float2*)(X3 + base + 128 + c);
          xc[mt][rh][nt] = *(const float2*)(X3 + base + 256 + c);
        }
      }
    float acc[2][6][4];
    #pragma unroll
    for (int mt=0;mt<2;mt++)
      #pragma unroll
      for (int j=0;j<6;j++)
        #pragma unroll
        for (int q=0;q<4;q++) acc[mt][j][q] = 0.f;
    #pragma unroll
    for (int k8=0;k8<16;++k8) {
      uint32_t a[2][4];
      #pragma unroll
      for (int mt=0;mt<2;mt++) {
        const float* ap = Ar + (mt*16 + g)*132 + k8*8 + t4;
        a[mt][0] = __float_as_uint(ap[0]);
        a[mt][1] = __float_as_uint(ap[8*132]);
        a[mt][2] = __float_as_uint(ap[4]);
        a[mt][3] = __float_as_uint(ap[8*132+4]);
      }
      float4 bv0 = *(const float4*)(Bp + ((k8*24 +      w)*32 + lane)*4);
      float4 bv1 = *(const float4*)(Bp + ((k8*24 +  8 + w)*32 + lane)*4);
      float4 bv2 = *(const float4*)(Bp + ((k8*24 + 16 + w)*32 + lane)*4);
      uint32_t bb[6][2];
      bb[0][0]=__float_as_uint(bv0.x); bb[0][1]=__float_as_uint(bv0.y);
      bb[1][0]=__float_as_uint(bv0.z); bb[1][1]=__float_as_uint(bv0.w);
      bb[2][0]=__float_as_uint(bv1.x); bb[2][1]=__float_as_uint(bv1.y);
      bb[3][0]=__float_as_uint(bv1.z); bb[3][1]=__float_as_uint(bv1.w);
      bb[4][0]=__float_as_uint(bv2.x); bb[4][1]=__float_as_uint(bv2.y);
      bb[5][0]=__float_as_uint(bv2.z); bb[5][1]=__float_as_uint(bv2.w);
      #pragma unroll
      for (int mt=0;mt<2;mt++)
        #pragma unroll
        for (int j=0;j<6;j++)
          mma8(acc[mt][j], a[mt], bb[j]);
    }
    #pragma unroll
    for (int mt=0;mt<2;mt++)
      #pragma unroll
      for (int rh=0;rh<2;rh++) {
        int row = mt*16 + rh*8 + g;
        float atv = at[mt][rh];
        #pragma unroll
        for (int nt=0;nt<2;nt++) {
          int c = (2*w+nt)*8 + 2*t4;
          float hn0, hn1;
          {
            float u  = sig_(xu[mt][rh][nt].x + acc[mt][nt][rh*2]);
            float r  = sig_(xr[mt][rh][nt].x + acc[mt][2+nt][rh*2]);
            float cc = tanh_(xc[mt][rh][nt].x + r*acc[mt][4+nt][rh*2]);
            float uu = atv*u;
            float ho = h[mt][rh][nt][0];
            hn0 = (1.f - uu)*ho + uu*cc;
            h[mt][rh][nt][0] = hn0;
          }
          {
            float u  = sig_(xu[mt][rh][nt].y + acc[mt][nt][rh*2+1]);
            float r  = sig_(xr[mt][rh][nt].y + acc[mt][2+nt][rh*2+1]);
            float cc = tanh_(xc[mt][rh][nt].y + r*acc[mt][4+nt][rh*2+1]);
            float uu = atv*u;
            float ho = h[mt][rh][nt][1];
            hn1 = (1.f - uu)*ho + uu*cc;
            h[mt][rh][nt][1] = hn1;
          }
          float2 rt = {tf32r(hn0), tf32r(hn1)};
          *(float2*)(Aw + row*132 + c) = rt;
        }
      }
    __syncthreads();
  }
  #pragma unroll
  for (int mt=0;mt<2;mt++)
    #pragma unroll
    for (int rh=0;rh<2;rh++) {
      int row = mt*16 + rh*8 + g;
      #pragma unroll
      for (int nt=0;nt<2;nt++) {
        int c = (2*w+nt)*8 + 2*t4;
        float2 o = {h[mt][rh][nt][0], h[mt][rh][nt][1]};
        *(float2*)(g_hfin + (long long)(b0+row)*128 + c) = o;
      }
    }
}

// ------------- fused attention: hs,news -> a1 -> a2 -> ats -------------
// persistent: grid=148, 256 threads, processes 64-row blocks
__global__ __launch_bounds__(256, 1)
void att_fused(const float* __restrict__ hs, const float* __restrict__ inputs,
               const float* __restrict__ Wcatp, const float* __restrict__ W2p,
               const float* __restrict__ b2, const float* __restrict__ W3,
               const float* __restrict__ b3, const float* __restrict__ nterm) {
  extern __shared__ float sm[];
  float* As  = sm;                 // 64*260 = 16640
  float* Bp  = sm + 16640;         // 16384 (reused as a1s, stride 132)
  float* W2s = Bp + 16384;         // 8192 (packed W2 fragments)
  float* a2s = W2s + 8192;         // 64*68 = 4352
  float* W3s = a2s + 4352;         // 64
  const int tid = threadIdx.x;     // 256
  const int lane = tid & 31, wid = tid >> 5;
  const int wm = wid & 1, wn = wid >> 1;
  const int wm3 = wid & 3, wn3 = wid >> 2;
  const int g = lane >> 2, t4 = lane & 3;
  const float b3v = b3[0];

  { // load packed W2 fragments once
    const float4* src = (const float4*)W2p;
    float4* dst = (float4*)W2s;
    #pragma unroll
    for (int it = 0; it < 8; ++it) dst[it*256 + tid] = src[it*256 + tid];
    if (tid < 64) W3s[tid] = W3[tid];
  }
  const float4* Wc4 = (const float4*)Wcatp;
  float4* Bp4 = (float4*)Bp;

  for (long long blk = blockIdx.x; blk < BT/64; blk += gridDim.x) {
    const long long m0 = blk * 64;
    __syncthreads();   // protect As / a2s from previous iteration readers
    // stage 1: build A = [hs | hs*news] (tf32) — 64 rows x 256
    #pragma unroll
    for (int it = 0; it < 16; ++it) {
      int idx = it*256 + tid;
      int r = idx >> 6, q = idx & 63;
      long long row = m0 + r;
      int b = (int)(row / T);
      if (q < 32) {
        float4 h = *(const float4*)(hs + row*128 + 4*q);
        float* dst = As + r*260 + 4*q;
        dst[0]=tf32r(h.x); dst[1]=tf32r(h.y); dst[2]=tf32r(h.z); dst[3]=tf32r(h.w);
      } else {
        int qq = q - 32;
        float4 h  = *(const float4*)(hs + row*128 + 4*qq);
        float4 nw = *(const float4*)(inputs + ((long long)b*(T+1) + T)*128 + 4*qq);
        float* dst = As + r*260 + 128 + 4*qq;
        dst[0]=tf32r(h.x*nw.x); dst[1]=tf32r(h.y*nw.y);
        dst[2]=tf32r(h.z*nw.z); dst[3]=tf32r(h.w*nw.w);
      }
    }
    // layer 1 mainloop (K=256, two 128-chunks)
    float acc[2][4][4];
    #pragma unroll
    for (int mt=0;mt<2;mt++)
      #pragma unroll
      for (int nt=0;nt<4;nt++)
        #pragma unroll
        for (int q=0;q<4;q++) acc[mt][nt][q] = 0.f;
    for (int kc = 0; kc < 2; ++kc) {
      __syncthreads();   // kc0: As ready & Bp(a1s) free; kc1: prior readers done
      #pragma unroll
      for (int it = 0; it < 16; ++it) {
        int f = it*256 + tid;
        int k8 = f >> 8, rem = f & 255;
        Bp4[f] = Wc4[((long long)(kc*16 + k8)*8)*32 + rem];
      }
      __syncthreads();
      #pragma unroll
      for (int k8 = 0; k8 < 16; ++k8) {
        uint32_t a[2][4];
        #pragma unroll
        for (int mt=0;mt<2;mt++) {
          const float* ap = As + (wm*32 + mt*16 + g)*260 + kc*128 + k8*8 + t4;
          a[mt][0] = __float_as_uint(ap[0]);
          a[mt][1] = __float_as_uint(ap[8*260]);
          a[mt][2] = __float_as_uint(ap[4]);
          a[mt][3] = __float_as_uint(ap[8*260+4]);
        }
        float4 b40 = Bp4[(k8*8 + wn*2    )*32 + lane];
        float4 b41 = Bp4[(k8*8 + wn*2 + 1)*32 + lane];
        uint32_t bb[4][2];
        bb[0][0]=__float_as_uint(b40.x); bb[0][1]=__float_as_uint(b40.y);
        bb[1][0]=__float_as_uint(b40.z); bb[1][1]=__float_as_uint(b40.w);
        bb[2][0]=__float_as_uint(b41.x); bb[2][1]=__float_as_uint(b41.y);
        bb[3][0]=__float_as_uint(b41.z); bb[3][1]=__float_as_uint(b41.w);
        #pragma unroll
        for (int mt=0;mt<2;mt++)
          #pragma unroll
          for (int nt=0;nt<4;nt++)
            mma8(acc[mt][nt], a[mt], bb[nt]);
      }
    }
    __syncthreads();   // all warps done reading Bp -> reuse as a1s
    float* a1s = Bp;
    #pragma unroll
    for (int mt=0;mt<2;mt++) {
      int row0 = wm*32 + mt*16 + g;
      #pragma unroll
      for (int nt=0;nt<4;nt++) {
        int col = wn*32 + nt*8 + 2*t4;
        #pragma unroll
        for (int h=0; h<2; ++h) {
          int row = row0 + 8*h;
          long long rowg = m0 + row;
          const float* np = nterm + (long long)(rowg / T)*128;
          a1s[row*132 + col]     = tf32r(fmaxf(acc[mt][nt][2*h+0] + np[col],   0.f));
          a1s[row*132 + col + 1] = tf32r(fmaxf(acc[mt][nt][2*h+1] + np[col+1], 0.f));
        }
      }
    }
    __syncthreads();
    // layer 2 (tensor): a2 = relu(a1 @ W2 + b2), 64x64
    {
      float acc2[4][4];
      #pragma unroll
      for (int nt=0;nt<4;nt++)
        #pragma unroll
        for (int q=0;q<4;q++) acc2[nt][q] = 0.f;
      const float4* W2p4 = (const float4*)W2s;
      #pragma unroll
      for (int k8 = 0; k8 < 16; ++k8) {
        uint32_t a[4];
        const float* ap = a1s + (wm3*16 + g)*132 + k8*8 + t4;
        a[0] = __float_as_uint(ap[0]);
        a[1] = __float_as_uint(ap[8*132]);
        a[2] = __float_as_uint(ap[4]);
        a[3] = __float_as_uint(ap[8*132+4]);
        float4 b40 = W2p4[(k8*4 + wn3*2    )*32 + lane];
        float4 b41 = W2p4[(k8*4 + wn3*2 + 1)*32 + lane];
        uint32_t bb[4][2];
        bb[0][0]=__float_as_uint(b40.x); bb[0][1]=__float_as_uint(b40.y);
        bb[1][0]=__float_as_uint(b40.z); bb[1][1]=__float_as_uint(b40.w);
        bb[2][0]=__float_as_uint(b41.x); bb[2][1]=__float_as_uint(b41.y);
        bb[3][0]=__float_as_uint(b41.z); bb[3][1]=__float_as_uint(b41.w);
        #pragma unroll
        for (int nt=0;nt<4;nt++)
          mma8(acc2[nt], a, bb[nt]);
      }
      #pragma unroll
      for (int nt=0;nt<4;nt++) {
        int col = wn3*32 + nt*8 + 2*t4;
        float bc0 = b2[col], bc1 = b2[col+1];
        #pragma unroll
        for (int h=0; h<2; ++h) {
          int row = wm3*16 + g + 8*h;
          a2s[row*68 + col]     = fmaxf(acc2[nt][2*h+0] + bc0, 0.f);
          a2s[row*68 + col + 1] = fmaxf(acc2[nt][2*h+1] + bc1, 0.f);
        }
      }
    }
    __syncthreads();
    // layer 3: score
    if (tid < 64) {
      float accv = b3v;
      #pragma unroll 8
      for (int cc=0; cc<64; ++cc) accv = fmaf(a2s[tid*68 + cc], W3s[cc], accv);
      g_ats[m0 + tid] = sigf(accv);
    }
  }
}

// ------------------------------ head ------------------------------
__global__ void head_kernel(const float* __restrict__ inputs,
                            const float* __restrict__ gamma, const float* __restrict__ beta,
                            const float* __restrict__ mean,  const float* __restrict__ var,
                            const float* __restrict__ W1, const float* __restrict__ bb1,
                            const float* __restrict__ W2, const float* __restrict__ bb2,
                            const float* __restrict__ fW, const float* __restrict__ fb,
                            float* __restrict__ out) {
  extern __shared__ float sm[];
  float* xs  = sm;          // 32*256
  float* y1s = xs + 8192;   // 32*256
  float* y2s = y1s + 8192;  // 32*128
  const int tid = threadIdx.x;   // 256
  const int b0 = blockIdx.x * 32;
  for (int r = 0; r < 32; ++r) {
    int k = tid;
    int bb = b0 + r;
    float v = (k < 128) ? g_hfin[bb*128 + k]
                        : inputs[((long long)bb*(T+1) + T)*128 + (k - 128)];
    float nv = (v - mean[k]) * rsqrtf(var[k] + BN_EPS) * gamma[k] + beta[k];
    xs[r*256 + k] = nv;
  }
  __syncthreads();
  {
    float acc[32];
    #pragma unroll
    for (int r=0;r<32;r++) acc[r] = bb1[tid];
    for (int k=0;k<256;++k) {
      float w = W1[k*256 + tid];
      #pragma unroll
      for (int r=0;r<32;r++) acc[r] = fmaf(xs[r*256+k], w, acc[r]);
    }
    #pragma unroll
    for (int r=0;r<32;r++) {
      float v = acc[r];
      y1s[r*256 + tid] = v >= 0.f ? v : LEAKY*v;
    }
  }
  __syncthreads();
  if (tid < 128) {
    float acc[32];
    #pragma unroll
    for (int r=0;r<32;r++) acc[r] = bb2[tid];
    for (int k=0;k<256;++k) {
      float w = W2[k*128 + tid];
      #pragma unroll
      for (int r=0;r<32;r++) acc[r] = fmaf(y1s[r*256+k], w, acc[r]);
    }
    #pragma unroll
    for (int r=0;r<32;r++) {
      float v = acc[r];
      y2s[r*128 + tid] = v >= 0.f ? v : LEAKY*v;
    }
  }
  __syncthreads();
  if (tid < 32) {
    float acc = fb[0];
    for (int k=0;k<128;++k) acc = fmaf(y2s[tid*128+k], fW[k], acc);
    out[b0 + tid] = sigf(acc);
  }
}

// ------------------------------ launch ------------------------------
extern "C" void kernel_launch(void* const* d_in, const int* in_sizes, int n_in,
                              void* d_out, int out_size) {
  (void)in_sizes; (void)n_in; (void)out_size;
  const float* inputs  = (const float*)d_in[0];
  const float* gru_W   = (const float*)d_in[1];
  const float* gru_U   = (const float*)d_in[2];
  const float* gru_b   = (const float*)d_in[3];
  const float* att_W1  = (const float*)d_in[4];
  const float* att_b1  = (const float*)d_in[5];
  const float* att_W2  = (const float*)d_in[6];
  const float* att_b2  = (const float*)d_in[7];
  const float* att_W3  = (const float*)d_in[8];
  const float* att_b3  = (const float*)d_in[9];
  const float* au_Wu   = (const float*)d_in[10];
  const float* au_bu   = (const float*)d_in[11];
  const float* au_Uu   = (const float*)d_in[12];
  const float* au_Wr   = (const float*)d_in[13];
  const float* au_br   = (const float*)d_in[14];
  const float* au_Ur   = (const float*)d_in[15];
  const float* au_Wc   = (const float*)d_in[16];
  const float* au_bc   = (const float*)d_in[17];
  const float* au_Uc   = (const float*)d_in[18];
  const float* bn_gamma= (const float*)d_in[19];
  const float* bn_beta = (const float*)d_in[20];
  const float* bn_mean = (const float*)d_in[21];
  const float* bn_var  = (const float*)d_in[22];
  const float* d_W1    = (const float*)d_in[23];
  const float* d_b1    = (const float*)d_in[24];
  const float* d_W2    = (const float*)d_in[25];
  const float* d_b2    = (const float*)d_in[26];
  const float* f_W     = (const float*)d_in[27];
  const float* f_b     = (const float*)d_in[28];
  float* out = (float*)d_out;

  const size_t sm_gemm = (64*132 + 16384)*sizeof(float);      // 99328
  const size_t sm_scan = (49152 + 2*32*132)*sizeof(float);    // 230400
  const size_t sm_attf = (16640 + 16384 + 8192 + 4352 + 64)*sizeof(float); // 182528
  const size_t sm_head = (8192*2 + 4096)*sizeof(float);
  cudaFuncSetAttribute(gemm_v2,        cudaFuncAttributeMaxDynamicSharedMemorySize, (int)sm_gemm);
  cudaFuncSetAttribute(gru_scan_mma,   cudaFuncAttributeMaxDynamicSharedMemorySize, (int)sm_scan);
  cudaFuncSetAttribute(augru_scan_mma, cudaFuncAttributeMaxDynamicSharedMemorySize, (int)sm_scan);
  cudaFuncSetAttribute(att_fused,      cudaFuncAttributeMaxDynamicSharedMemorySize, (int)sm_attf);
  cudaFuncSetAttribute(head_kernel,    cudaFuncAttributeMaxDynamicSharedMemorySize, (int)sm_head);

  float *p_Xp, *p_hs, *p_X3, *p_newsterm, *p_Wau, *p_bau, *p_W1bc, *p_Uau, *p_Wcat;
  float *p_Upg, *p_Upa, *p_WpgW, *p_Wpau, *p_Wp1bc, *p_Wpcat, *p_Wpatt2;
  cudaGetSymbolAddress((void**)&p_Xp,       g_Xp);
  cudaGetSymbolAddress((void**)&p_hs,       g_hs);
  cudaGetSymbolAddress((void**)&p_X3,       g_X3);
  cudaGetSymbolAddress((void**)&p_newsterm, g_newsterm);
  cudaGetSymbolAddress((void**)&p_Wau,      g_Wau);
  cudaGetSymbolAddress((void**)&p_bau,      g_bau);
  cudaGetSymbolAddress((void**)&p_W1bc,     g_W1bc);
  cudaGetSymbolAddress((void**)&p_Uau,      g_Uau);
  cudaGetSymbolAddress((void**)&p_Wcat,     g_Wcat);
  cudaGetSymbolAddress((void**)&p_Upg,      g_Upack_gru);
  cudaGetSymbolAddress((void**)&p_Upa,      g_Upack_au);
  cudaGetSymbolAddress((void**)&p_WpgW,     g_Wp_gruW);
  cudaGetSymbolAddress((void**)&p_Wpau,     g_Wp_au);
  cudaGetSymbolAddress((void**)&p_Wp1bc,    g_Wp_1bc);
  cudaGetSymbolAddress((void**)&p_Wpcat,    g_Wp_cat);
  cudaGetSymbolAddress((void**)&p_Wpatt2,   g_Wp_att2);

  // 1) pack AU weights + attention folded weights
  prep_kernel<<<192, 256>>>(au_Wu, au_bu, au_Wr, au_br, au_Wc, au_bc,
                            au_Uu, au_Ur, au_Uc, att_W1);
  // 1b) fragment-pack all weight matrices
  pack_frag_n<<<192, 256>>>(gru_U,   p_Upg,    384, 49152);
  pack_frag_n<<<192, 256>>>(p_Uau,   p_Upa,    384, 49152);
  pack_frag_n<<<192, 256>>>(gru_W,   p_WpgW,   384, 49152);
  pack_frag_n<<<192, 256>>>(p_Wau,   p_Wpau,   384, 49152);
  pack_frag_n<<<64,  256>>>(p_W1bc,  p_Wp1bc,  128, 16384);
  pack_frag_n<<<128, 256>>>(p_Wcat,  p_Wpcat,  128, 32768);
  pack_frag_n<<<32,  256>>>(att_W2,  p_Wpatt2, 64,  8192);
  // 2) Xp = hist @ gru_W + gru_b[0]
  gemm_v2<<<dim3(BT/64, 3), 256, sm_gemm>>>(inputs, T, (long long)(T+1)*128, 128,
                                            p_WpgW, 24, gru_b, p_Xp, 384);
  // 3) newsterm = news @ (W1B+W1C) + b1
  gemm_v2<<<dim3(B/64, 1), 256, sm_gemm>>>(inputs + (long long)T*128, 1, (long long)(T+1)*128, 128,
                                           p_Wp1bc, 8, att_b1, p_newsterm, 128);
  // 4) GRU recurrence -> hs
  gru_scan_mma<<<B/32, 256, sm_scan>>>(p_Xp, p_Upg, gru_b + 384, p_hs);
  // 5) fused attention -> g_ats
  att_fused<<<148, 256, sm_attf>>>(p_hs, inputs, p_Wpcat, p_Wpatt2,
                                   att_b2, att_W3, att_b3, p_newsterm);
  // 6) X3 = hs @ [Wu|Wr|Wc] + [bu|br|bc]
  gemm_v2<<<dim3(BT/64, 3), 256, sm_gemm>>>(p_hs, 1<<30, 0LL, 128,
                                            p_Wpau, 24, p_bau, p_X3, 384);
  // 7) AUGRU recurrence -> hfin
  augru_scan_mma<<<B/32, 256, sm_scan>>>(p_X3, p_Upa);
  // 8) BN + dense head -> out
  head_kernel<<<B/32, 256, sm_head>>>(inputs, bn_gamma, bn_beta, bn_mean, bn_var,
                                      d_W1, d_b1, d_W2, d_b2, f_W, f_b, out);
}

// round 6
// speedup vs baseline: 3.6366x; 1.0458x over previous
#include <cuda_runtime.h>
#include <math.h>
#include <stdint.h>

#define B  4096
#define T  50
#define U  128
#define N3 384
#define BT (B*T)
#define BN_EPS 1e-3f
#define LEAKY  3e-4f

// ------------ scratch (device globals; no allocation allowed) ------------
__device__ float g_Xp[BT*N3];        // GRU input projection
__device__ float g_hs[BT*U];         // GRU hidden states
__device__ float g_X3[BT*N3];        // AUGRU input projections
__device__ float g_ats[BT];          // attention scores
__device__ float g_hfin[B*U];        // AUGRU final state
__device__ float g_newsterm[B*U];    // news@(W1B+W1C)+b1
__device__ float g_Wau[U*N3];        // packed input  [Wu|Wr|Wc]
__device__ float g_Uau[U*N3];        // packed recur  [Uu|Ur|Uc]
__device__ float g_bau[N3];          // packed [bu|br|bc]
__device__ float g_Wcat[2*U*U];      // [W1A-W1B ; W1D]  (256 x 128)
__device__ float g_W1bc[U*U];        // W1B + W1C
__device__ float g_Upack_gru[128*N3];// fragment-ordered gru_U
__device__ float g_Upack_au[128*N3]; // fragment-ordered [Uu|Ur|Uc]
__device__ float g_Wp_gruW[128*N3];  // fragment-ordered gru_W
__device__ float g_Wp_au[128*N3];    // fragment-ordered [Wu|Wr|Wc]
__device__ float g_Wp_1bc[128*128];  // fragment-ordered W1B+W1C
__device__ float g_Wp_cat[256*128];  // fragment-ordered Wcat (K=256)
__device__ float g_Wp_att2[128*64];  // fragment-ordered att_W2

__device__ __forceinline__ float sigf(float x){ return 1.f/(1.f+expf(-x)); }
__device__ __forceinline__ float tanha(float x){
  float y; asm("tanh.approx.f32 %0, %1;" : "=f"(y) : "f"(x)); return y;
}
__device__ __forceinline__ float sigt(float x){ return fmaf(tanha(0.5f*x), 0.5f, 0.5f); }
__device__ __forceinline__ float tf32r(float f){
  uint32_t r; asm("cvt.rna.tf32.f32 %0, %1;" : "=r"(r) : "f"(f));
  return __uint_as_float(r);
}
__device__ __forceinline__ void mma8(float* d, const uint32_t* a, const uint32_t* b){
  asm volatile("mma.sync.aligned.m16n8k8.row.col.f32.tf32.tf32.f32 "
               "{%0,%1,%2,%3}, {%4,%5,%6,%7}, {%8,%9}, {%0,%1,%2,%3};"
               : "+f"(d[0]), "+f"(d[1]), "+f"(d[2]), "+f"(d[3])
               : "r"(a[0]), "r"(a[1]), "r"(a[2]), "r"(a[3]), "r"(b[0]), "r"(b[1]));
}

// ------------------------------- prep -------------------------------
__global__ void prep_kernel(const float* __restrict__ Wu, const float* __restrict__ bu,
                            const float* __restrict__ Wr, const float* __restrict__ br,
                            const float* __restrict__ Wc, const float* __restrict__ bc,
                            const float* __restrict__ Uu, const float* __restrict__ Ur,
                            const float* __restrict__ Uc,
                            const float* __restrict__ attW1) {
  int id = blockIdx.x*blockDim.x + threadIdx.x;
  if (id < U*N3) {
    int k = id / N3, c = id % N3;
    float w, u;
    if (c < 128)      { w = Wu[k*128 + c];       u = Uu[k*128 + c]; }
    else if (c < 256) { w = Wr[k*128 + (c-128)]; u = Ur[k*128 + (c-128)]; }
    else              { w = Wc[k*128 + (c-256)]; u = Uc[k*128 + (c-256)]; }
    g_Wau[id] = w;
    g_Uau[id] = u;
  }
  if (id < N3)
    g_bau[id] = (id < 128) ? bu[id] : (id < 256 ? br[id-128] : bc[id-256]);
  if (id < 2*U*U) {
    int k = id / 128, c = id % 128;
    float v;
    if (k < 128) v = attW1[k*128 + c] - attW1[U*U + k*128 + c];     // W1A - W1B
    else         v = attW1[3*U*U + (k-128)*128 + c];                // W1D
    g_Wcat[id] = v;
  }
  if (id < U*U)
    g_W1bc[id] = attW1[U*U + id] + attW1[2*U*U + id];
}

// --------------- pack all weights fragment-ordered (tf32), one launch ---------------
__device__ __forceinline__ void pack_one(const float* __restrict__ Um, float* __restrict__ P,
                                         int N, int idx) {
  int q = idx & 3, lane = (idx >> 2) & 31;
  int Ntp = N >> 4;
  int tp = (idx >> 7) % Ntp, k8 = (idx >> 7) / Ntp;
  int tile = 2*tp + (q >> 1), r = q & 1;
  int k = k8*8 + (lane & 3) + 4*r;
  int n = tile*8 + (lane >> 2);
  P[idx] = tf32r(Um[k*N + n]);
}

__global__ void pack_all(const float* __restrict__ gruU, const float* __restrict__ gruW,
                         const float* __restrict__ attW2) {
  int idx = blockIdx.x*256 + threadIdx.x;   // 253952 total
  if (idx < 49152)        pack_one(gruU,    g_Upack_gru, 384, idx);
  else if (idx < 98304)   pack_one(g_Uau,   g_Upack_au,  384, idx - 49152);
  else if (idx < 147456)  pack_one(gruW,    g_Wp_gruW,   384, idx - 98304);
  else if (idx < 196608)  pack_one(g_Wau,   g_Wp_au,     384, idx - 147456);
  else if (idx < 212992)  pack_one(g_W1bc,  g_Wp_1bc,    128, idx - 196608);
  else if (idx < 245760)  pack_one(g_Wcat,  g_Wp_cat,    128, idx - 212992);
  else if (idx < 253952)  pack_one(attW2,   g_Wp_att2,   64,  idx - 245760);
}

// --------------------- tf32 GEMM, packed-B, K=128 ---------------------
__global__ void gemm_v2(const float* __restrict__ A, int P, long long GS, int RS,
                        const float* __restrict__ Bpk, int Ntp,
                        const float* __restrict__ bias, float* __restrict__ C, int ldc) {
  extern __shared__ float sm[];
  float* As = sm;               // 64 x 132
  float* Bp = sm + 64*132;      // 16384 floats
  const int m0 = blockIdx.x * 64;
  const int c0 = blockIdx.y * 128;
  const int tp0 = blockIdx.y * 8;
  const int tid = threadIdx.x;          // 256
  const int kq = tid >> 5, cq = tid & 31;
  const int lane = tid & 31, wid = tid >> 5;
  const int wm = wid & 1, wn = wid >> 1;
  const int g = lane >> 2, t4 = lane & 3;

  #pragma unroll
  for (int it = 0; it < 8; ++it) {
    int r = kq + 8*it;
    int m = m0 + r;
    const float* ap = A + (long long)(m/P)*GS + (long long)(m%P)*RS;
    float4 v = *(const float4*)(ap + 4*cq);
    float* dst = As + r*132 + 4*cq;
    dst[0]=tf32r(v.x); dst[1]=tf32r(v.y); dst[2]=tf32r(v.z); dst[3]=tf32r(v.w);
  }
  {
    const float4* src = (const float4*)Bpk;
    float4* dst = (float4*)Bp;
    #pragma unroll
    for (int it = 0; it < 16; ++it) {
      int f = it*256 + tid;
      int k8 = f >> 8, rem = f & 255;
      dst[f] = src[((long long)k8*Ntp + tp0)*32 + rem];
    }
  }
  __syncthreads();

  float acc[2][4][4];
  #pragma unroll
  for (int mt=0;mt<2;mt++)
    #pragma unroll
    for (int nt=0;nt<4;nt++)
      #pragma unroll
      for (int q=0;q<4;q++) acc[mt][nt][q] = 0.f;

  const float4* bp4 = (const float4*)Bp;
  #pragma unroll
  for (int k8 = 0; k8 < 16; ++k8) {
    uint32_t a[2][4];
    #pragma unroll
    for (int mt=0;mt<2;mt++) {
      const float* ap = As + (wm*32 + mt*16 + g)*132 + k8*8 + t4;
      a[mt][0] = __float_as_uint(ap[0]);
      a[mt][1] = __float_as_uint(ap[8*132]);
      a[mt][2] = __float_as_uint(ap[4]);
      a[mt][3] = __float_as_uint(ap[8*132+4]);
    }
    float4 b40 = bp4[(k8*8 + wn*2    )*32 + lane];
    float4 b41 = bp4[(k8*8 + wn*2 + 1)*32 + lane];
    uint32_t bb[4][2];
    bb[0][0]=__float_as_uint(b40.x); bb[0][1]=__float_as_uint(b40.y);
    bb[1][0]=__float_as_uint(b40.z); bb[1][1]=__float_as_uint(b40.w);
    bb[2][0]=__float_as_uint(b41.x); bb[2][1]=__float_as_uint(b41.y);
    bb[3][0]=__float_as_uint(b41.z); bb[3][1]=__float_as_uint(b41.w);
    #pragma unroll
    for (int mt=0;mt<2;mt++)
      #pragma unroll
      for (int nt=0;nt<4;nt++)
        mma8(acc[mt][nt], a[mt], bb[nt]);
  }
  #pragma unroll
  for (int mt=0;mt<2;mt++) {
    int row0 = m0 + wm*32 + mt*16 + g;
    #pragma unroll
    for (int nt=0;nt<4;nt++) {
      int col = c0 + wn*32 + nt*8 + 2*t4;
      #pragma unroll
      for (int h=0; h<2; ++h) {
        int row = row0 + 8*h;
        float2 o = {acc[mt][nt][2*h+0] + bias[col], acc[mt][nt][2*h+1] + bias[col+1]};
        *(float2*)(C + (long long)row*ldc + col) = o;
      }
    }
  }
}

// -------------------- GRU scan, tensor-core (32 rows/CTA) --------------------
__global__ __launch_bounds__(256, 1)
void gru_scan_mma(const float* __restrict__ Xp, const float* __restrict__ Bpack,
                  const float* __restrict__ brec, float* __restrict__ hs) {
  extern __shared__ float sm[];
  float* Bp = sm;                 // 49152
  float* Ab = sm + 49152;         // 2 * 32*132
  const int tid = threadIdx.x;    // 256
  const int w = tid >> 5, lane = tid & 31;
  const int g = lane >> 2, t4 = lane & 3;
  const int b0 = blockIdx.x * 32;
  #pragma unroll
  for (int it = 0; it < 48; ++it) {
    int o = (it*256 + tid)*4;
    *(float4*)(Bp + o) = *(const float4*)(Bpack + o);
  }
  for (int i = tid; i < 2*32*132; i += 256) Ab[i] = 0.f;
  float2 bz[2], brr[2], bh[2];
  #pragma unroll
  for (int nt=0; nt<2; ++nt) {
    int c = (2*w+nt)*8 + 2*t4;
    bz[nt]  = *(const float2*)(brec + c);
    brr[nt] = *(const float2*)(brec + 128 + c);
    bh[nt]  = *(const float2*)(brec + 256 + c);
  }
  float h[2][2][2][2];
  #pragma unroll
  for (int a1=0;a1<2;a1++)
    #pragma unroll
    for (int a2=0;a2<2;a2++)
      #pragma unroll
      for (int a3=0;a3<2;a3++) { h[a1][a2][a3][0]=0.f; h[a1][a2][a3][1]=0.f; }
  __syncthreads();

  for (int t = 0; t < T; ++t) {
    const float* Ar = Ab + (t & 1) * (32*132);
    float* Aw = Ab + ((t & 1) ^ 1) * (32*132);
    float2 xz[2][2][2], xr[2][2][2], xh[2][2][2];
    #pragma unroll
    for (int mt=0;mt<2;mt++)
      #pragma unroll
      for (int rh=0;rh<2;rh++) {
        long long base = ((long long)(b0 + mt*16 + rh*8 + g)*T + t)*N3 + 2*t4;
        #pragma unroll
        for (int nt=0;nt<2;nt++) {
          int c = (2*w+nt)*8;
          xz[mt][rh][nt] = *(const float2*)(Xp + base + c);
          xr[mt][rh][nt] = *(const float2*)(Xp + base + 128 + c);
          xh[mt][rh][nt] = *(const float2*)(Xp + base + 256 + c);
        }
      }
    float acc[2][6][4];
    #pragma unroll
    for (int mt=0;mt<2;mt++)
      #pragma unroll
      for (int j=0;j<6;j++)
        #pragma unroll
        for (int q=0;q<4;q++) acc[mt][j][q] = 0.f;
    #pragma unroll
    for (int k8=0;k8<16;++k8) {
      uint32_t a[2][4];
      #pragma unroll
      for (int mt=0;mt<2;mt++) {
        const float* ap = Ar + (mt*16 + g)*132 + k8*8 + t4;
        a[mt][0] = __float_as_uint(ap[0]);
        a[mt][1] = __float_as_uint(ap[8*132]);
        a[mt][2] = __float_as_uint(ap[4]);
        a[mt][3] = __float_as_uint(ap[8*132+4]);
      }
      float4 bv0 = *(const float4*)(Bp + ((k8*24 +      w)*32 + lane)*4);
      float4 bv1 = *(const float4*)(Bp + ((k8*24 +  8 + w)*32 + lane)*4);
      float4 bv2 = *(const float4*)(Bp + ((k8*24 + 16 + w)*32 + lane)*4);
      uint32_t bb[6][2];
      bb[0][0]=__float_as_uint(bv0.x); bb[0][1]=__float_as_uint(bv0.y);
      bb[1][0]=__float_as_uint(bv0.z); bb[1][1]=__float_as_uint(bv0.w);
      bb[2][0]=__float_as_uint(bv1.x); bb[2][1]=__float_as_uint(bv1.y);
      bb[3][0]=__float_as_uint(bv1.z); bb[3][1]=__float_as_uint(bv1.w);
      bb[4][0]=__float_as_uint(bv2.x); bb[4][1]=__float_as_uint(bv2.y);
      bb[5][0]=__float_as_uint(bv2.z); bb[5][1]=__float_as_uint(bv2.w);
      #pragma unroll
      for (int mt=0;mt<2;mt++)
        #pragma unroll
        for (int j=0;j<6;j++)
          mma8(acc[mt][j], a[mt], bb[j]);
    }
    #pragma unroll
    for (int mt=0;mt<2;mt++)
      #pragma unroll
      for (int rh=0;rh<2;rh++) {
        int row = mt*16 + rh*8 + g;
        long long grow = ((long long)(b0+row)*T + t)*128;
        #pragma unroll
        for (int nt=0;nt<2;nt++) {
          int c = (2*w+nt)*8 + 2*t4;
          float hn0, hn1;
          {
            float z  = sigt(xz[mt][rh][nt].x + acc[mt][nt][rh*2]     + bz[nt].x);
            float r  = sigt(xr[mt][rh][nt].x + acc[mt][2+nt][rh*2]   + brr[nt].x);
            float hc = tanha(xh[mt][rh][nt].x + r*(acc[mt][4+nt][rh*2] + bh[nt].x));
            float ho = h[mt][rh][nt][0];
            hn0 = z*ho + (1.f - z)*hc;
            h[mt][rh][nt][0] = hn0;
          }
          {
            float z  = sigt(xz[mt][rh][nt].y + acc[mt][nt][rh*2+1]     + bz[nt].y);
            float r  = sigt(xr[mt][rh][nt].y + acc[mt][2+nt][rh*2+1]   + brr[nt].y);
            float hc = tanha(xh[mt][rh][nt].y + r*(acc[mt][4+nt][rh*2+1] + bh[nt].y));
            float ho = h[mt][rh][nt][1];
            hn1 = z*ho + (1.f - z)*hc;
            h[mt][rh][nt][1] = hn1;
          }
          float2 o = {hn0, hn1};
          *(float2*)(hs + grow + c) = o;
          float2 rt = {tf32r(hn0), tf32r(hn1)};
          *(float2*)(Aw + row*132 + c) = rt;
        }
      }
    __syncthreads();
  }
}

// -------------------- AUGRU scan, tensor-core --------------------
__global__ __launch_bounds__(256, 1)
void augru_scan_mma(const float* __restrict__ X3, const float* __restrict__ Bpack) {
  extern __shared__ float sm[];
  float* Bp = sm;
  float* Ab = sm + 49152;
  const int tid = threadIdx.x;
  const int w = tid >> 5, lane = tid & 31;
  const int g = lane >> 2, t4 = lane & 3;
  const int b0 = blockIdx.x * 32;
  #pragma unroll
  for (int it = 0; it < 48; ++it) {
    int o = (it*256 + tid)*4;
    *(float4*)(Bp + o) = *(const float4*)(Bpack + o);
  }
  for (int i = tid; i < 2*32*132; i += 256) Ab[i] = 0.f;
  float h[2][2][2][2];
  #pragma unroll
  for (int a1=0;a1<2;a1++)
    #pragma unroll
    for (int a2=0;a2<2;a2++)
      #pragma unroll
      for (int a3=0;a3<2;a3++) { h[a1][a2][a3][0]=0.f; h[a1][a2][a3][1]=0.f; }
  __syncthreads();

  for (int t = 0; t < T; ++t) {
    const float* Ar = Ab + (t & 1) * (32*132);
    float* Aw = Ab + ((t & 1) ^ 1) * (32*132);
    float2 xu[2][2][2], xr[2][2][2], xc[2][2][2];
    float at[2][2];
    #pragma unroll
    for (int mt=0;mt<2;mt++)
      #pragma unroll
      for (int rh=0;rh<2;rh++) {
        long long rowg = (long long)(b0 + mt*16 + rh*8 + g)*T + t;
        at[mt][rh] = g_ats[rowg];
        long long base = rowg*N3 + 2*t4;
        #pragma unroll
        for (int nt=0;nt<2;nt++) {
          int c = (2*w+nt)*8;
          xu[mt][rh][nt] = *(const float2*)(X3 + base + c);
          xr[mt][rh][nt] = *(const float2*)(X3 + base + 128 + c);
          xc[mt][rh][nt] = *(const float2*)(X3 + base + 256 + c);
        }
      }
    float acc[2][6][4];
    #pragma unroll
    for (int mt=0;mt<2;mt++)
      #pragma unroll
      for (int j=0;j<6;j++)
        #pragma unroll
        for (int q=0;q<4;q++) acc[mt][j][q] = 0.f;
    #pragma unroll
    for (int k8=0;k8<16;++k8) {
      uint32_t a[2][4];
      #pragma unroll
      for (int mt=0;mt<2;mt++) {
        const float* ap = Ar + (mt*16 + g)*132 + k8*8 + t4;
        a[mt][0] = __float_as_uint(ap[0]);
        a[mt][1] = __float_as_uint(ap[8*132]);
        a[mt][2] = __float_as_uint(ap[4]);
        a[mt][3] = __float_as_uint(ap[8*132+4]);
      }
      float4 bv0 = *(const float4*)(Bp + ((k8*24 +      w)*32 + lane)*4);
      float4 bv1 = *(const float4*)(Bp + ((k8*24 +  8 + w)*32 + lane)*4);
      float4 bv2 = *(const float4*)(Bp + ((k8*24 + 16 + w)*32 + lane)*4);
      uint32_t bb[6][2];
      bb[0][0]=__float_as_uint(bv0.x); bb[0][1]=__float_as_uint(bv0.y);
      bb[1][0]=__float_as_uint(bv0.z); bb[1][1]=__float_as_uint(bv0.w);
      bb[2][0]=__float_as_uint(bv1.x); bb[2][1]=__float_as_uint(bv1.y);
      bb[3][0]=__float_as_uint(bv1.z); bb[3][1]=__float_as_uint(bv1.w);
      bb[4][0]=__float_as_uint(bv2.x); bb[4][1]=__float_as_uint(bv2.y);
      bb[5][0]=__float_as_uint(bv2.z); bb[5][1]=__float_as_uint(bv2.w);
      #pragma unroll
      for (int mt=0;mt<2;mt++)
        #pragma unroll
        for (int j=0;j<6;j++)
          mma8(acc[mt][j], a[mt], bb[j]);
    }
    #pragma unroll
    for (int mt=0;mt<2;mt++)
      #pragma unroll
      for (int rh=0;rh<2;rh++) {
        int row = mt*16 + rh*8 + g;
        float atv = at[mt][rh];
        #pragma unroll
        for (int nt=0;nt<2;nt++) {
          int c = (2*w+nt)*8 + 2*t4;
          float hn0, hn1;
          {
            float u  = sigt(xu[mt][rh][nt].x + acc[mt][nt][rh*2]);
            float r  = sigt(xr[mt][rh][nt].x + acc[mt][2+nt][rh*2]);
            float cc = tanha(xc[mt][rh][nt].x + r*acc[mt][4+nt][rh*2]);
            float uu = atv*u;
            float ho = h[mt][rh][nt][0];
            hn0 = (1.f - uu)*ho + uu*cc;
            h[mt][rh][nt][0] = hn0;
          }
          {
            float u  = sigt(xu[mt][rh][nt].y + acc[mt][nt][rh*2+1]);
            float r  = sigt(xr[mt][rh][nt].y + acc[mt][2+nt][rh*2+1]);
            float cc = tanha(xc[mt][rh][nt].y + r*acc[mt][4+nt][rh*2+1]);
            float uu = atv*u;
            float ho = h[mt][rh][nt][1];
            hn1 = (1.f - uu)*ho + uu*cc;
            h[mt][rh][nt][1] = hn1;
          }
          float2 rt = {tf32r(hn0), tf32r(hn1)};
          *(float2*)(Aw + row*132 + c) = rt;
        }
      }
    __syncthreads();
  }
  #pragma unroll
  for (int mt=0;mt<2;mt++)
    #pragma unroll
    for (int rh=0;rh<2;rh++) {
      int row = mt*16 + rh*8 + g;
      #pragma unroll
      for (int nt=0;nt<2;nt++) {
        int c = (2*w+nt)*8 + 2*t4;
        float2 o = {h[mt][rh][nt][0], h[mt][rh][nt][1]};
        *(float2*)(g_hfin + (long long)(b0+row)*128 + c) = o;
      }
    }
}

// ------------- fused attention: hs,news -> a1 -> a2 -> ats -------------
__global__ __launch_bounds__(256, 1)
void att_fused(const float* __restrict__ hs, const float* __restrict__ inputs,
               const float* __restrict__ Wcatp, const float* __restrict__ W2p,
               const float* __restrict__ b2, const float* __restrict__ W3,
               const float* __restrict__ b3, const float* __restrict__ nterm) {
  extern __shared__ float sm[];
  float* As  = sm;                 // 64*260 = 16640
  float* Bp  = sm + 16640;         // 16384 (reused as a1s, stride 132)
  float* W2s = Bp + 16384;         // 8192 (packed W2 fragments)
  float* a2s = W2s + 8192;         // 64*68 = 4352
  float* W3s = a2s + 4352;         // 64
  const int tid = threadIdx.x;     // 256
  const int lane = tid & 31, wid = tid >> 5;
  const int wm = wid & 1, wn = wid >> 1;
  const int wm3 = wid & 3, wn3 = wid >> 2;
  const int g = lane >> 2, t4 = lane & 3;
  const float b3v = b3[0];

  {
    const float4* src = (const float4*)W2p;
    float4* dst = (float4*)W2s;
    #pragma unroll
    for (int it = 0; it < 8; ++it) dst[it*256 + tid] = src[it*256 + tid];
    if (tid < 64) W3s[tid] = W3[tid];
  }
  const float4* Wc4 = (const float4*)Wcatp;
  float4* Bp4 = (float4*)Bp;

  for (long long blk = blockIdx.x; blk < BT/64; blk += gridDim.x) {
    const long long m0 = blk * 64;
    __syncthreads();
    #pragma unroll
    for (int it = 0; it < 16; ++it) {
      int idx = it*256 + tid;
      int r = idx >> 6, q = idx & 63;
      long long row = m0 + r;
      int b = (int)(row / T);
      if (q < 32) {
        float4 h = *(const float4*)(hs + row*128 + 4*q);
        float* dst = As + r*260 + 4*q;
        dst[0]=tf32r(h.x); dst[1]=tf32r(h.y); dst[2]=tf32r(h.z); dst[3]=tf32r(h.w);
      } else {
        int qq = q - 32;
        float4 h  = *(const float4*)(hs + row*128 + 4*qq);
        float4 nw = *(const float4*)(inputs + ((long long)b*(T+1) + T)*128 + 4*qq);
        float* dst = As + r*260 + 128 + 4*qq;
        dst[0]=tf32r(h.x*nw.x); dst[1]=tf32r(h.y*nw.y);
        dst[2]=tf32r(h.z*nw.z); dst[3]=tf32r(h.w*nw.w);
      }
    }
    float acc[2][4][4];
    #pragma unroll
    for (int mt=0;mt<2;mt++)
      #pragma unroll
      for (int nt=0;nt<4;nt++)
        #pragma unroll
        for (int q=0;q<4;q++) acc[mt][nt][q] = 0.f;
    for (int kc = 0; kc < 2; ++kc) {
      __syncthreads();
      #pragma unroll
      for (int it = 0; it < 16; ++it) {
        int f = it*256 + tid;
        int k8 = f >> 8, rem = f & 255;
        Bp4[f] = Wc4[((long long)(kc*16 + k8)*8)*32 + rem];
      }
      __syncthreads();
      #pragma unroll
      for (int k8 = 0; k8 < 16; ++k8) {
        uint32_t a[2][4];
        #pragma unroll
        for (int mt=0;mt<2;mt++) {
          const float* ap = As + (wm*32 + mt*16 + g)*260 + kc*128 + k8*8 + t4;
          a[mt][0] = __float_as_uint(ap[0]);
          a[mt][1] = __float_as_uint(ap[8*260]);
          a[mt][2] = __float_as_uint(ap[4]);
          a[mt][3] = __float_as_uint(ap[8*260+4]);
        }
        float4 b40 = Bp4[(k8*8 + wn*2    )*32 + lane];
        float4 b41 = Bp4[(k8*8 + wn*2 + 1)*32 + lane];
        uint32_t bb[4][2];
        bb[0][0]=__float_as_uint(b40.x); bb[0][1]=__float_as_uint(b40.y);
        bb[1][0]=__float_as_uint(b40.z); bb[1][1]=__float_as_uint(b40.w);
        bb[2][0]=__float_as_uint(b41.x); bb[2][1]=__float_as_uint(b41.y);
        bb[3][0]=__float_as_uint(b41.z); bb[3][1]=__float_as_uint(b41.w);
        #pragma unroll
        for (int mt=0;mt<2;mt++)
          #pragma unroll
          for (int nt=0;nt<4;nt++)
            mma8(acc[mt][nt], a[mt], bb[nt]);
      }
    }
    __syncthreads();
    float* a1s = Bp;
    #pragma unroll
    for (int mt=0;mt<2;mt++) {
      int row0 = wm*32 + mt*16 + g;
      #pragma unroll
      for (int nt=0;nt<4;nt++) {
        int col = wn*32 + nt*8 + 2*t4;
        #pragma unroll
        for (int h=0; h<2; ++h) {
          int row = row0 + 8*h;
          long long rowg = m0 + row;
          const float* np = nterm + (long long)(rowg / T)*128;
          a1s[row*132 + col]     = tf32r(fmaxf(acc[mt][nt][2*h+0] + np[col],   0.f));
          a1s[row*132 + col + 1] = tf32r(fmaxf(acc[mt][nt][2*h+1] + np[col+1], 0.f));
        }
      }
    }
    __syncthreads();
    {
      float acc2[4][4];
      #pragma unroll
      for (int nt=0;nt<4;nt++)
        #pragma unroll
        for (int q=0;q<4;q++) acc2[nt][q] = 0.f;
      const float4* W2p4 = (const float4*)W2s;
      #pragma unroll
      for (int k8 = 0; k8 < 16; ++k8) {
        uint32_t a[4];
        const float* ap = a1s + (wm3*16 + g)*132 + k8*8 + t4;
        a[0] = __float_as_uint(ap[0]);
        a[1] = __float_as_uint(ap[8*132]);
        a[2] = __float_as_uint(ap[4]);
        a[3] = __float_as_uint(ap[8*132+4]);
        float4 b40 = W2p4[(k8*4 + wn3*2    )*32 + lane];
        float4 b41 = W2p4[(k8*4 + wn3*2 + 1)*32 + lane];
        uint32_t bb[4][2];
        bb[0][0]=__float_as_uint(b40.x); bb[0][1]=__float_as_uint(b40.y);
        bb[1][0]=__float_as_uint(b40.z); bb[1][1]=__float_as_uint(b40.w);
        bb[2][0]=__float_as_uint(b41.x); bb[2][1]=__float_as_uint(b41.y);
        bb[3][0]=__float_as_uint(b41.z); bb[3][1]=__float_as_uint(b41.w);
        #pragma unroll
        for (int nt=0;nt<4;nt++)
          mma8(acc2[nt], a, bb[nt]);
      }
      #pragma unroll
      for (int nt=0;nt<4;nt++) {
        int col = wn3*32 + nt*8 + 2*t4;
        float bc0 = b2[col], bc1 = b2[col+1];
        #pragma unroll
        for (int h=0; h<2; ++h) {
          int row = wm3*16 + g + 8*h;
          a2s[row*68 + col]     = fmaxf(acc2[nt][2*h+0] + bc0, 0.f);
          a2s[row*68 + col + 1] = fmaxf(acc2[nt][2*h+1] + bc1, 0.f);
        }
      }
    }
    __syncthreads();
    if (tid < 64) {
      float accv = b3v;
      #pragma unroll 8
      for (int cc=0; cc<64; ++cc) accv = fmaf(a2s[tid*68 + cc], W3s[cc], accv);
      g_ats[m0 + tid] = sigf(accv);
    }
  }
}

// ------------------------------ head ------------------------------
__global__ void head_kernel(const float* __restrict__ inputs,
                            const float* __restrict__ gamma, const float* __restrict__ beta,
                            const float* __restrict__ mean,  const float* __restrict__ var,
                            const float* __restrict__ W1, const float* __restrict__ bb1,
                            const float* __restrict__ W2, const float* __restrict__ bb2,
                            const float* __restrict__ fW, const float* __restrict__ fb,
                            float* __restrict__ out) {
  extern __shared__ float sm[];
  float* xs  = sm;          // 32*256
  float* y1s = xs + 8192;   // 32*256
  float* y2s = y1s + 8192;  // 32*128
  const int tid = threadIdx.x;   // 256
  const int b0 = blockIdx.x * 32;
  for (int r = 0; r < 32; ++r) {
    int k = tid;
    int bb = b0 + r;
    float v = (k < 128) ? g_hfin[bb*128 + k]
                        : inputs[((long long)bb*(T+1) + T)*128 + (k - 128)];
    float nv = (v - mean[k]) * rsqrtf(var[k] + BN_EPS) * gamma[k] + beta[k];
    xs[r*256 + k] = nv;
  }
  __syncthreads();
  {
    float acc[32];
    #pragma unroll
    for (int r=0;r<32;r++) acc[r] = bb1[tid];
    for (int k=0;k<256;++k) {
      float w = W1[k*256 + tid];
      #pragma unroll
      for (int r=0;r<32;r++) acc[r] = fmaf(xs[r*256+k], w, acc[r]);
    }
    #pragma unroll
    for (int r=0;r<32;r++) {
      float v = acc[r];
      y1s[r*256 + tid] = v >= 0.f ? v : LEAKY*v;
    }
  }
  __syncthreads();
  if (tid < 128) {
    float acc[32];
    #pragma unroll
    for (int r=0;r<32;r++) acc[r] = bb2[tid];
    for (int k=0;k<256;++k) {
      float w = W2[k*128 + tid];
      #pragma unroll
      for (int r=0;r<32;r++) acc[r] = fmaf(y1s[r*256+k], w, acc[r]);
    }
    #pragma unroll
    for (int r=0;r<32;r++) {
      float v = acc[r];
      y2s[r*128 + tid] = v >= 0.f ? v : LEAKY*v;
    }
  }
  __syncthreads();
  if (tid < 32) {
    float acc = fb[0];
    for (int k=0;k<128;++k) acc = fmaf(y2s[tid*128+k], fW[k], acc);
    out[b0 + tid] = sigf(acc);
  }
}

// ------------------------------ launch ------------------------------
extern "C" void kernel_launch(void* const* d_in, const int* in_sizes, int n_in,
                              void* d_out, int out_size) {
  (void)in_sizes; (void)n_in; (void)out_size;
  const float* inputs  = (const float*)d_in[0];
  const float* gru_W   = (const float*)d_in[1];
  const float* gru_U   = (const float*)d_in[2];
  const float* gru_b   = (const float*)d_in[3];
  const float* att_W1  = (const float*)d_in[4];
  const float* att_b1  = (const float*)d_in[5];
  const float* att_W2  = (const float*)d_in[6];
  const float* att_b2  = (const float*)d_in[7];
  const float* att_W3  = (const float*)d_in[8];
  const float* att_b3  = (const float*)d_in[9];
  const float* au_Wu   = (const float*)d_in[10];
  const float* au_bu   = (const float*)d_in[11];
  const float* au_Uu   = (const float*)d_in[12];
  const float* au_Wr   = (const float*)d_in[13];
  const float* au_br   = (const float*)d_in[14];
  const float* au_Ur   = (const float*)d_in[15];
  const float* au_Wc   = (const float*)d_in[16];
  const float* au_bc   = (const float*)d_in[17];
  const float* au_Uc   = (const float*)d_in[18];
  const float* bn_gamma= (const float*)d_in[19];
  const float* bn_beta = (const float*)d_in[20];
  const float* bn_mean = (const float*)d_in[21];
  const float* bn_var  = (const float*)d_in[22];
  const float* d_W1    = (const float*)d_in[23];
  const float* d_b1    = (const float*)d_in[24];
  const float* d_W2    = (const float*)d_in[25];
  const float* d_b2    = (const float*)d_in[26];
  const float* f_W     = (const float*)d_in[27];
  const float* f_b     = (const float*)d_in[28];
  float* out = (float*)d_out;

  const size_t sm_gemm = (64*132 + 16384)*sizeof(float);      // 99328
  const size_t sm_scan = (49152 + 2*32*132)*sizeof(float);    // 230400
  const size_t sm_attf = (16640 + 16384 + 8192 + 4352 + 64)*sizeof(float); // 182528
  const size_t sm_head = (8192*2 + 4096)*sizeof(float);
  cudaFuncSetAttribute(gemm_v2,        cudaFuncAttributeMaxDynamicSharedMemorySize, (int)sm_gemm);
  cudaFuncSetAttribute(gru_scan_mma,   cudaFuncAttributeMaxDynamicSharedMemorySize, (int)sm_scan);
  cudaFuncSetAttribute(augru_scan_mma, cudaFuncAttributeMaxDynamicSharedMemorySize, (int)sm_scan);
  cudaFuncSetAttribute(att_fused,      cudaFuncAttributeMaxDynamicSharedMemorySize, (int)sm_attf);
  cudaFuncSetAttribute(head_kernel,    cudaFuncAttributeMaxDynamicSharedMemorySize, (int)sm_head);

  float *p_Xp, *p_hs, *p_X3, *p_newsterm, *p_bau;
  float *p_Upg, *p_Upa, *p_WpgW, *p_Wpau, *p_Wp1bc, *p_Wpcat, *p_Wpatt2;
  cudaGetSymbolAddress((void**)&p_Xp,       g_Xp);
  cudaGetSymbolAddress((void**)&p_hs,       g_hs);
  cudaGetSymbolAddress((void**)&p_X3,       g_X3);
  cudaGetSymbolAddress((void**)&p_newsterm, g_newsterm);
  cudaGetSymbolAddress((void**)&p_bau,      g_bau);
  cudaGetSymbolAddress((void**)&p_Upg,      g_Upack_gru);
  cudaGetSymbolAddress((void**)&p_Upa,      g_Upack_au);
  cudaGetSymbolAddress((void**)&p_WpgW,     g_Wp_gruW);
  cudaGetSymbolAddress((void**)&p_Wpau,     g_Wp_au);
  cudaGetSymbolAddress((void**)&p_Wp1bc,    g_Wp_1bc);
  cudaGetSymbolAddress((void**)&p_Wpcat,    g_Wp_cat);
  cudaGetSymbolAddress((void**)&p_Wpatt2,   g_Wp_att2);

  // side stream + fork/join events (created per call; not device allocations)
  cudaStream_t s2;
  cudaStreamCreateWithFlags(&s2, cudaStreamNonBlocking);
  cudaEvent_t evFork, evJoin;
  cudaEventCreateWithFlags(&evFork, cudaEventDisableTiming);
  cudaEventCreateWithFlags(&evJoin, cudaEventDisableTiming);

  // 1) pack AU weights + attention folded weights, then all fragment packs
  prep_kernel<<<192, 256>>>(au_Wu, au_bu, au_Wr, au_br, au_Wc, au_bc,
                            au_Uu, au_Ur, au_Uc, att_W1);
  pack_all<<<992, 256>>>(gru_U, gru_W, att_W2);
  // 2) Xp = hist @ gru_W + gru_b[0]
  gemm_v2<<<dim3(BT/64, 3), 256, sm_gemm>>>(inputs, T, (long long)(T+1)*128, 128,
                                            p_WpgW, 24, gru_b, p_Xp, 384);
  // 3) newsterm = news @ (W1B+W1C) + b1
  gemm_v2<<<dim3(B/64, 1), 256, sm_gemm>>>(inputs + (long long)T*128, 1, (long long)(T+1)*128, 128,
                                           p_Wp1bc, 8, att_b1, p_newsterm, 128);
  // 4) GRU recurrence -> hs
  gru_scan_mma<<<B/32, 256, sm_scan>>>(p_Xp, p_Upg, gru_b + 384, p_hs);
  // fork: X3 gemm on s2, attention on main stream (both read hs only)
  cudaEventRecord(evFork, 0);
  cudaStreamWaitEvent(s2, evFork, 0);
  // 5) fused attention -> g_ats   (main stream)
  att_fused<<<148, 256, sm_attf>>>(p_hs, inputs, p_Wpcat, p_Wpatt2,
                                   att_b2, att_W3, att_b3, p_newsterm);
  // 6) X3 = hs @ [Wu|Wr|Wc] + [bu|br|bc]   (side stream)
  gemm_v2<<<dim3(BT/64, 3), 256, sm_gemm, s2>>>(p_hs, 1<<30, 0LL, 128,
                                                p_Wpau, 24, p_bau, p_X3, 384);
  cudaEventRecord(evJoin, s2);
  cudaStreamWaitEvent(0, evJoin, 0);
  // 7) AUGRU recurrence -> hfin (needs ats + X3)
  augru_scan_mma<<<B/32, 256, sm_scan>>>(p_X3, p_Upa);
  // 8) BN + dense head -> out
  head_kernel<<<B/32, 256, sm_head>>>(inputs, bn_gamma, bn_beta, bn_mean, bn_var,
                                      d_W1, d_b1, d_W2, d_b2, f_W, f_b, out);
}

// round 7
// speedup vs baseline: 3.9553x; 1.0877x over previous
#include <cuda_runtime.h>
#include <cuda_bf16.h>
#include <math.h>
#include <stdint.h>

#define B  4096
#define T  50
#define U  128
#define N3 384
#define BT (B*T)
#define BN_EPS 1e-3f
#define LEAKY  3e-4f

// ------------ scratch (device globals; no allocation allowed) ------------
__device__ float g_Xp[BT*N3];        // GRU input projection
__device__ float g_hs[BT*U];         // GRU hidden states
__device__ float g_X3[BT*N3];        // AUGRU input projections
__device__ float g_ats[BT];          // attention scores
__device__ float g_hfin[B*U];        // AUGRU final state
__device__ float g_newsterm[B*U];    // news@(W1B+W1C)+b1
__device__ float g_Wau[U*N3];        // packed input  [Wu|Wr|Wc]
__device__ float g_Uau[U*N3];        // packed recur  [Uu|Ur|Uc]
__device__ float g_bau[N3];          // packed [bu|br|bc]
__device__ float g_Wcat[2*U*U];      // [W1A-W1B ; W1D]  (256 x 128)
__device__ float g_W1bc[U*U];        // W1B + W1C
__device__ uint32_t g_Ubf_gru[24576];// bf16 fragment-ordered gru_U   (96 KB)
__device__ uint32_t g_Ubf_au[24576]; // bf16 fragment-ordered [Uu|Ur|Uc]
__device__ float g_Wp_gruW[128*N3];  // tf32 fragment-ordered gru_W
__device__ float g_Wp_au[128*N3];    // tf32 fragment-ordered [Wu|Wr|Wc]
__device__ float g_Wp_1bc[128*128];  // tf32 fragment-ordered W1B+W1C
__device__ float g_Wp_cat[256*128];  // tf32 fragment-ordered Wcat (K=256)
__device__ float g_Wp_att2[128*64];  // tf32 fragment-ordered att_W2

__device__ __forceinline__ float sigf(float x){ return 1.f/(1.f+expf(-x)); }
__device__ __forceinline__ float tanha(float x){
  float y; asm("tanh.approx.f32 %0, %1;" : "=f"(y) : "f"(x)); return y;
}
__device__ __forceinline__ float sigt(float x){ return fmaf(tanha(0.5f*x), 0.5f, 0.5f); }
__device__ __forceinline__ float tf32r(float f){
  uint32_t r; asm("cvt.rna.tf32.f32 %0, %1;" : "=r"(r) : "f"(f));
  return __uint_as_float(r);
}
__device__ __forceinline__ uint32_t bf2(float lo, float hi){
  __nv_bfloat162 v;
  v.x = __float2bfloat16(lo); v.y = __float2bfloat16(hi);
  return *(uint32_t*)&v;
}
__device__ __forceinline__ void mma8(float* d, const uint32_t* a, const uint32_t* b){
  asm volatile("mma.sync.aligned.m16n8k8.row.col.f32.tf32.tf32.f32 "
               "{%0,%1,%2,%3}, {%4,%5,%6,%7}, {%8,%9}, {%0,%1,%2,%3};"
               : "+f"(d[0]), "+f"(d[1]), "+f"(d[2]), "+f"(d[3])
               : "r"(a[0]), "r"(a[1]), "r"(a[2]), "r"(a[3]), "r"(b[0]), "r"(b[1]));
}
__device__ __forceinline__ void mma16(float* d, const uint32_t* a, const uint32_t* b){
  asm volatile("mma.sync.aligned.m16n8k16.row.col.f32.bf16.bf16.f32 "
               "{%0,%1,%2,%3}, {%4,%5,%6,%7}, {%8,%9}, {%0,%1,%2,%3};"
               : "+f"(d[0]), "+f"(d[1]), "+f"(d[2]), "+f"(d[3])
               : "r"(a[0]), "r"(a[1]), "r"(a[2]), "r"(a[3]), "r"(b[0]), "r"(b[1]));
}

// ------------------------------- prep -------------------------------
__global__ void prep_kernel(const float* __restrict__ Wu, const float* __restrict__ bu,
                            const float* __restrict__ Wr, const float* __restrict__ br,
                            const float* __restrict__ Wc, const float* __restrict__ bc,
                            const float* __restrict__ Uu, const float* __restrict__ Ur,
                            const float* __restrict__ Uc,
                            const float* __restrict__ attW1) {
  int id = blockIdx.x*blockDim.x + threadIdx.x;
  if (id < U*N3) {
    int k = id / N3, c = id % N3;
    float w, u;
    if (c < 128)      { w = Wu[k*128 + c];       u = Uu[k*128 + c]; }
    else if (c < 256) { w = Wr[k*128 + (c-128)]; u = Ur[k*128 + (c-128)]; }
    else              { w = Wc[k*128 + (c-256)]; u = Uc[k*128 + (c-256)]; }
    g_Wau[id] = w;
    g_Uau[id] = u;
  }
  if (id < N3)
    g_bau[id] = (id < 128) ? bu[id] : (id < 256 ? br[id-128] : bc[id-256]);
  if (id < 2*U*U) {
    int k = id / 128, c = id % 128;
    float v;
    if (k < 128) v = attW1[k*128 + c] - attW1[U*U + k*128 + c];     // W1A - W1B
    else         v = attW1[3*U*U + (k-128)*128 + c];                // W1D
    g_Wcat[id] = v;
  }
  if (id < U*U)
    g_W1bc[id] = attW1[U*U + id] + attW1[2*U*U + id];
}

// --------------- pack weights fragment-ordered, one launch ---------------
// tf32 (m16n8k8): P[((k8*Ntp + tp)*32 + lane)*4 + q], tile=2*tp+(q>>1), reg=q&1
__device__ __forceinline__ void pack_one(const float* __restrict__ Um, float* __restrict__ P,
                                         int N, int idx) {
  int q = idx & 3, lane = (idx >> 2) & 31;
  int Ntp = N >> 4;
  int tp = (idx >> 7) % Ntp, k8 = (idx >> 7) / Ntp;
  int tile = 2*tp + (q >> 1), r = q & 1;
  int k = k8*8 + (lane & 3) + 4*r;
  int n = tile*8 + (lane >> 2);
  P[idx] = tf32r(Um[k*N + n]);
}
// bf16 (m16n8k16), N=384 only: P[((k16*24 + tp)*32 + lane)*4 + q] (uint32 units)
// tile=2*tp+(q>>1), reg=q&1: k = k16*16 + 2*(lane&3) + 8*reg (+1 in hi), n = tile*8 + lane>>2
__device__ __forceinline__ void pack_bf16_one(const float* __restrict__ Um,
                                              uint32_t* __restrict__ P, int idx) {
  int q = idx & 3, lane = (idx >> 2) & 31;
  int tp = (idx >> 7) % 24, k16 = (idx >> 7) / 24;
  int tile = 2*tp + (q >> 1), r = q & 1;
  int k = k16*16 + 2*(lane & 3) + 8*r;
  int n = tile*8 + (lane >> 2);
  P[idx] = bf2(Um[k*N3 + n], Um[(k+1)*N3 + n]);
}

__global__ void pack_all(const float* __restrict__ gruU, const float* __restrict__ gruW,
                         const float* __restrict__ attW2) {
  int idx = blockIdx.x*256 + threadIdx.x;   // 204800 total
  if (idx < 24576)        pack_bf16_one(gruU,  g_Ubf_gru, idx);
  else if (idx < 49152)   pack_bf16_one(g_Uau, g_Ubf_au,  idx - 24576);
  else if (idx < 98304)   pack_one(gruW,    g_Wp_gruW,   384, idx - 49152);
  else if (idx < 147456)  pack_one(g_Wau,   g_Wp_au,     384, idx - 98304);
  else if (idx < 163840)  pack_one(g_W1bc,  g_Wp_1bc,    128, idx - 147456);
  else if (idx < 196608)  pack_one(g_Wcat,  g_Wp_cat,    128, idx - 163840);
  else if (idx < 204800)  pack_one(attW2,   g_Wp_att2,   64,  idx - 196608);
}

// --------------------- tf32 GEMM, packed-B, K=128 ---------------------
__global__ void gemm_v2(const float* __restrict__ A, int P, long long GS, int RS,
                        const float* __restrict__ Bpk, int Ntp,
                        const float* __restrict__ bias, float* __restrict__ C, int ldc) {
  extern __shared__ float sm[];
  float* As = sm;               // 64 x 132
  float* Bp = sm + 64*132;      // 16384 floats
  const int m0 = blockIdx.x * 64;
  const int c0 = blockIdx.y * 128;
  const int tp0 = blockIdx.y * 8;
  const int tid = threadIdx.x;          // 256
  const int kq = tid >> 5, cq = tid & 31;
  const int lane = tid & 31, wid = tid >> 5;
  const int wm = wid & 1, wn = wid >> 1;
  const int g = lane >> 2, t4 = lane & 3;

  #pragma unroll
  for (int it = 0; it < 8; ++it) {
    int r = kq + 8*it;
    int m = m0 + r;
    const float* ap = A + (long long)(m/P)*GS + (long long)(m%P)*RS;
    float4 v = *(const float4*)(ap + 4*cq);
    float* dst = As + r*132 + 4*cq;
    dst[0]=tf32r(v.x); dst[1]=tf32r(v.y); dst[2]=tf32r(v.z); dst[3]=tf32r(v.w);
  }
  {
    const float4* src = (const float4*)Bpk;
    float4* dst = (float4*)Bp;
    #pragma unroll
    for (int it = 0; it < 16; ++it) {
      int f = it*256 + tid;
      int k8 = f >> 8, rem = f & 255;
      dst[f] = src[((long long)k8*Ntp + tp0)*32 + rem];
    }
  }
  __syncthreads();

  float acc[2][4][4];
  #pragma unroll
  for (int mt=0;mt<2;mt++)
    #pragma unroll
    for (int nt=0;nt<4;nt++)
      #pragma unroll
      for (int q=0;q<4;q++) acc[mt][nt][q] = 0.f;

  const float4* bp4 = (const float4*)Bp;
  #pragma unroll
  for (int k8 = 0; k8 < 16; ++k8) {
    uint32_t a[2][4];
    #pragma unroll
    for (int mt=0;mt<2;mt++) {
      const float* ap = As + (wm*32 + mt*16 + g)*132 + k8*8 + t4;
      a[mt][0] = __float_as_uint(ap[0]);
      a[mt][1] = __float_as_uint(ap[8*132]);
      a[mt][2] = __float_as_uint(ap[4]);
      a[mt][3] = __float_as_uint(ap[8*132+4]);
    }
    float4 b40 = bp4[(k8*8 + wn*2    )*32 + lane];
    float4 b41 = bp4[(k8*8 + wn*2 + 1)*32 + lane];
    uint32_t bb[4][2];
    bb[0][0]=__float_as_uint(b40.x); bb[0][1]=__float_as_uint(b40.y);
    bb[1][0]=__float_as_uint(b40.z); bb[1][1]=__float_as_uint(b40.w);
    bb[2][0]=__float_as_uint(b41.x); bb[2][1]=__float_as_uint(b41.y);
    bb[3][0]=__float_as_uint(b41.z); bb[3][1]=__float_as_uint(b41.w);
    #pragma unroll
    for (int mt=0;mt<2;mt++)
      #pragma unroll
      for (int nt=0;nt<4;nt++)
        mma8(acc[mt][nt], a[mt], bb[nt]);
  }
  #pragma unroll
  for (int mt=0;mt<2;mt++) {
    int row0 = m0 + wm*32 + mt*16 + g;
    #pragma unroll
    for (int nt=0;nt<4;nt++) {
      int col = c0 + wn*32 + nt*8 + 2*t4;
      #pragma unroll
      for (int h=0; h<2; ++h) {
        int row = row0 + 8*h;
        float2 o = {acc[mt][nt][2*h+0] + bias[col], acc[mt][nt][2*h+1] + bias[col+1]};
        *(float2*)(C + (long long)row*ldc + col) = o;
      }
    }
  }
}

// -------------------- GRU scan, bf16 tensor-core (32 rows/CTA) --------------------
// SMEM: Bp 96KB (bf16 pack) + 2 x (32 x 136 bf16) A buffers
#define A_STRIDE 136
#define A_BUF    (32*A_STRIDE)   // bf16 elements per buffer
__global__ __launch_bounds__(256, 1)
void gru_scan_mma(const float* __restrict__ Xp, const uint32_t* __restrict__ Bpack,
                  const float* __restrict__ brec, float* __restrict__ hs) {
  extern __shared__ char smc[];
  uint32_t* Bp = (uint32_t*)smc;                       // 24576 u32
  __nv_bfloat16* Ab = (__nv_bfloat16*)(smc + 98304);   // 2 * A_BUF
  const int tid = threadIdx.x;    // 256
  const int w = tid >> 5, lane = tid & 31;
  const int g = lane >> 2, t4 = lane & 3;
  const int b0 = blockIdx.x * 32;
  #pragma unroll
  for (int it = 0; it < 24; ++it)
    ((float4*)Bp)[it*256 + tid] = ((const float4*)Bpack)[it*256 + tid];
  for (int i = tid; i < 2*A_BUF/2; i += 256) ((uint32_t*)Ab)[i] = 0u;
  float2 bz[2], brr[2], bh[2];
  #pragma unroll
  for (int nt=0; nt<2; ++nt) {
    int c = (2*w+nt)*8 + 2*t4;
    bz[nt]  = *(const float2*)(brec + c);
    brr[nt] = *(const float2*)(brec + 128 + c);
    bh[nt]  = *(const float2*)(brec + 256 + c);
  }
  float h[2][2][2][2];
  #pragma unroll
  for (int a1=0;a1<2;a1++)
    #pragma unroll
    for (int a2=0;a2<2;a2++)
      #pragma unroll
      for (int a3=0;a3<2;a3++) { h[a1][a2][a3][0]=0.f; h[a1][a2][a3][1]=0.f; }
  __syncthreads();

  for (int t = 0; t < T; ++t) {
    const __nv_bfloat16* Ar = Ab + (t & 1) * A_BUF;
    __nv_bfloat16* Aw = Ab + ((t & 1) ^ 1) * A_BUF;
    float2 xz[2][2][2], xr[2][2][2], xh[2][2][2];
    #pragma unroll
    for (int mt=0;mt<2;mt++)
      #pragma unroll
      for (int rh=0;rh<2;rh++) {
        long long base = ((long long)(b0 + mt*16 + rh*8 + g)*T + t)*N3 + 2*t4;
        #pragma unroll
        for (int nt=0;nt<2;nt++) {
          int c = (2*w+nt)*8;
          xz[mt][rh][nt] = *(const float2*)(Xp + base + c);
          xr[mt][rh][nt] = *(const float2*)(Xp + base + 128 + c);
          xh[mt][rh][nt] = *(const float2*)(Xp + base + 256 + c);
        }
      }
    float acc[2][6][4];
    #pragma unroll
    for (int mt=0;mt<2;mt++)
      #pragma unroll
      for (int j=0;j<6;j++)
        #pragma unroll
        for (int q=0;q<4;q++) acc[mt][j][q] = 0.f;
    #pragma unroll
    for (int k16=0;k16<8;++k16) {
      uint32_t a[2][4];
      #pragma unroll
      for (int mt=0;mt<2;mt++) {
        const __nv_bfloat16* ap = Ar + (mt*16 + g)*A_STRIDE + k16*16 + 2*t4;
        a[mt][0] = *(const uint32_t*)(ap);
        a[mt][1] = *(const uint32_t*)(ap + 8*A_STRIDE);
        a[mt][2] = *(const uint32_t*)(ap + 8);
        a[mt][3] = *(const uint32_t*)(ap + 8*A_STRIDE + 8);
      }
      uint4 bv0 = ((const uint4*)Bp)[(k16*24 +      w)*32 + lane];
      uint4 bv1 = ((const uint4*)Bp)[(k16*24 +  8 + w)*32 + lane];
      uint4 bv2 = ((const uint4*)Bp)[(k16*24 + 16 + w)*32 + lane];
      uint32_t bb[6][2];
      bb[0][0]=bv0.x; bb[0][1]=bv0.y; bb[1][0]=bv0.z; bb[1][1]=bv0.w;
      bb[2][0]=bv1.x; bb[2][1]=bv1.y; bb[3][0]=bv1.z; bb[3][1]=bv1.w;
      bb[4][0]=bv2.x; bb[4][1]=bv2.y; bb[5][0]=bv2.z; bb[5][1]=bv2.w;
      #pragma unroll
      for (int mt=0;mt<2;mt++)
        #pragma unroll
        for (int j=0;j<6;j++)
          mma16(acc[mt][j], a[mt], bb[j]);
    }
    #pragma unroll
    for (int mt=0;mt<2;mt++)
      #pragma unroll
      for (int rh=0;rh<2;rh++) {
        int row = mt*16 + rh*8 + g;
        long long grow = ((long long)(b0+row)*T + t)*128;
        #pragma unroll
        for (int nt=0;nt<2;nt++) {
          int c = (2*w+nt)*8 + 2*t4;
          float hn0, hn1;
          {
            float z  = sigt(xz[mt][rh][nt].x + acc[mt][nt][rh*2]     + bz[nt].x);
            float r  = sigt(xr[mt][rh][nt].x + acc[mt][2+nt][rh*2]   + brr[nt].x);
            float hc = tanha(xh[mt][rh][nt].x + r*(acc[mt][4+nt][rh*2] + bh[nt].x));
            float ho = h[mt][rh][nt][0];
            hn0 = z*ho + (1.f - z)*hc;
            h[mt][rh][nt][0] = hn0;
          }
          {
            float z  = sigt(xz[mt][rh][nt].y + acc[mt][nt][rh*2+1]     + bz[nt].y);
            float r  = sigt(xr[mt][rh][nt].y + acc[mt][2+nt][rh*2+1]   + brr[nt].y);
            float hc = tanha(xh[mt][rh][nt].y + r*(acc[mt][4+nt][rh*2+1] + bh[nt].y));
            float ho = h[mt][rh][nt][1];
            hn1 = z*ho + (1.f - z)*hc;
            h[mt][rh][nt][1] = hn1;
          }
          float2 o = {hn0, hn1};
          *(float2*)(hs + grow + c) = o;
          *(uint32_t*)(Aw + row*A_STRIDE + c) = bf2(hn0, hn1);
        }
      }
    __syncthreads();
  }
}

// -------------------- AUGRU scan, bf16 tensor-core --------------------
__global__ __launch_bounds__(256, 1)
void augru_scan_mma(const float* __restrict__ X3, const uint32_t* __restrict__ Bpack) {
  extern __shared__ char smc[];
  uint32_t* Bp = (uint32_t*)smc;
  __nv_bfloat16* Ab = (__nv_bfloat16*)(smc + 98304);
  const int tid = threadIdx.x;
  const int w = tid >> 5, lane = tid & 31;
  const int g = lane >> 2, t4 = lane & 3;
  const int b0 = blockIdx.x * 32;
  #pragma unroll
  for (int it = 0; it < 24; ++it)
    ((float4*)Bp)[it*256 + tid] = ((const float4*)Bpack)[it*256 + tid];
  for (int i = tid; i < 2*A_BUF/2; i += 256) ((uint32_t*)Ab)[i] = 0u;
  float h[2][2][2][2];
  #pragma unroll
  for (int a1=0;a1<2;a1++)
    #pragma unroll
    for (int a2=0;a2<2;a2++)
      #pragma unroll
      for (int a3=0;a3<2;a3++) { h[a1][a2][a3][0]=0.f; h[a1][a2][a3][1]=0.f; }
  __syncthreads();

  for (int t = 0; t < T; ++t) {
    const __nv_bfloat16* Ar = Ab + (t & 1) * A_BUF;
    __nv_bfloat16* Aw = Ab + ((t & 1) ^ 1) * A_BUF;
    float2 xu[2][2][2], xr[2][2][2], xc[2][2][2];
    float at[2][2];
    #pragma unroll
    for (int mt=0;mt<2;mt++)
      #pragma unroll
      for (int rh=0;rh<2;rh++) {
        long long rowg = (long long)(b0 + mt*16 + rh*8 + g)*T + t;
        at[mt][rh] = g_ats[rowg];
        long long base = rowg*N3 + 2*t4;
        #pragma unroll
        for (int nt=0;nt<2;nt++) {
          int c = (2*w+nt)*8;
          xu[mt][rh][nt] = *(const float2*)(X3 + base + c);
          xr[mt][rh][nt] = *(const float2*)(X3 + base + 128 + c);
          xc[mt][rh][nt] = *(const float2*)(X3 + base + 256 + c);
        }
      }
    float acc[2][6][4];
    #pragma unroll
    for (int mt=0;mt<2;mt++)
      #pragma unroll
      for (int j=0;j<6;j++)
        #pragma unroll
        for (int q=0;q<4;q++) acc[mt][j][q] = 0.f;
    #pragma unroll
    for (int k16=0;k16<8;++k16) {
      uint32_t a[2][4];
      #pragma unroll
      for (int mt=0;mt<2;mt++) {
        const __nv_bfloat16* ap = Ar + (mt*16 + g)*A_STRIDE + k16*16 + 2*t4;
        a[mt][0] = *(const uint32_t*)(ap);
        a[mt][1] = *(const uint32_t*)(ap + 8*A_STRIDE);
        a[mt][2] = *(const uint32_t*)(ap + 8);
        a[mt][3] = *(const uint32_t*)(ap + 8*A_STRIDE + 8);
      }
      uint4 bv0 = ((const uint4*)Bp)[(k16*24 +      w)*32 + lane];
      uint4 bv1 = ((const uint4*)Bp)[(k16*24 +  8 + w)*32 + lane];
      uint4 bv2 = ((const uint4*)Bp)[(k16*24 + 16 + w)*32 + lane];
      uint32_t bb[6][2];
      bb[0][0]=bv0.x; bb[0][1]=bv0.y; bb[1][0]=bv0.z; bb[1][1]=bv0.w;
      bb[2][0]=bv1.x; bb[2][1]=bv1.y; bb[3][0]=bv1.z; bb[3][1]=bv1.w;
      bb[4][0]=bv2.x; bb[4][1]=bv2.y; bb[5][0]=bv2.z; bb[5][1]=bv2.w;
      #pragma unroll
      for (int mt=0;mt<2;mt++)
        #pragma unroll
        for (int j=0;j<6;j++)
          mma16(acc[mt][j], a[mt], bb[j]);
    }
    #pragma unroll
    for (int mt=0;mt<2;mt++)
      #pragma unroll
      for (int rh=0;rh<2;rh++) {
        int row = mt*16 + rh*8 + g;
        float atv = at[mt][rh];
        #pragma unroll
        for (int nt=0;nt<2;nt++) {
          int c = (2*w+nt)*8 + 2*t4;
          float hn0, hn1;
          {
            float u  = sigt(xu[mt][rh][nt].x + acc[mt][nt][rh*2]);
            float r  = sigt(xr[mt][rh][nt].x + acc[mt][2+nt][rh*2]);
            float cc = tanha(xc[mt][rh][nt].x + r*acc[mt][4+nt][rh*2]);
            float uu = atv*u;
            float ho = h[mt][rh][nt][0];
            hn0 = (1.f - uu)*ho + uu*cc;
            h[mt][rh][nt][0] = hn0;
          }
          {
            float u  = sigt(xu[mt][rh][nt].y + acc[mt][nt][rh*2+1]);
            float r  = sigt(xr[mt][rh][nt].y + acc[mt][2+nt][rh*2+1]);
            float cc = tanha(xc[mt][rh][nt].y + r*acc[mt][4+nt][rh*2+1]);
            float uu = atv*u;
            float ho = h[mt][rh][nt][1];
            hn1 = (1.f - uu)*ho + uu*cc;
            h[mt][rh][nt][1] = hn1;
          }
          *(uint32_t*)(Aw + row*A_STRIDE + c) = bf2(hn0, hn1);
        }
      }
    __syncthreads();
  }
  #pragma unroll
  for (int mt=0;mt<2;mt++)
    #pragma unroll
    for (int rh=0;rh<2;rh++) {
      int row = mt*16 + rh*8 + g;
      #pragma unroll
      for (int nt=0;nt<2;nt++) {
        int c = (2*w+nt)*8 + 2*t4;
        float2 o = {h[mt][rh][nt][0], h[mt][rh][nt][1]};
        *(float2*)(g_hfin + (long long)(b0+row)*128 + c) = o;
      }
    }
}

// ------------- fused attention: hs,news -> a1 -> a2 -> ats -------------
__global__ __launch_bounds__(256, 1)
void att_fused(const float* __restrict__ hs, const float* __restrict__ inputs,
               const float* __restrict__ Wcatp, const float* __restrict__ W2p,
               const float* __restrict__ b2, const float* __restrict__ W3,
               const float* __restrict__ b3, const float* __restrict__ nterm) {
  extern __shared__ float sm[];
  float* As  = sm;                 // 64*260 = 16640
  float* Bp  = sm + 16640;         // 16384 (reused as a1s, stride 132)
  float* W2s = Bp + 16384;         // 8192 (packed W2 fragments)
  float* a2s = W2s + 8192;         // 64*68 = 4352
  float* W3s = a2s + 4352;         // 64
  const int tid = threadIdx.x;     // 256
  const int lane = tid & 31, wid = tid >> 5;
  const int wm = wid & 1, wn = wid >> 1;
  const int wm3 = wid & 3, wn3 = wid >> 2;
  const int g = lane >> 2, t4 = lane & 3;
  const float b3v = b3[0];

  {
    const float4* src = (const float4*)W2p;
    float4* dst = (float4*)W2s;
    #pragma unroll
    for (int it = 0; it < 8; ++it) dst[it*256 + tid] = src[it*256 + tid];
    if (tid < 64) W3s[tid] = W3[tid];
  }
  const float4* Wc4 = (const float4*)Wcatp;
  float4* Bp4 = (float4*)Bp;

  for (long long blk = blockIdx.x; blk < BT/64; blk += gridDim.x) {
    const long long m0 = blk * 64;
    __syncthreads();
    #pragma unroll
    for (int it = 0; it < 16; ++it) {
      int idx = it*256 + tid;
      int r = idx >> 6, q = idx & 63;
      long long row = m0 + r;
      int b = (int)(row / T);
      if (q < 32) {
        float4 h = *(const float4*)(hs + row*128 + 4*q);
        float* dst = As + r*260 + 4*q;
        dst[0]=tf32r(h.x); dst[1]=tf32r(h.y); dst[2]=tf32r(h.z); dst[3]=tf32r(h.w);
      } else {
        int qq = q - 32;
        float4 h  = *(const float4*)(hs + row*128 + 4*qq);
        float4 nw = *(const float4*)(inputs + ((long long)b*(T+1) + T)*128 + 4*qq);
        float* dst = As + r*260 + 128 + 4*qq;
        dst[0]=tf32r(h.x*nw.x); dst[1]=tf32r(h.y*nw.y);
        dst[2]=tf32r(h.z*nw.z); dst[3]=tf32r(h.w*nw.w);
      }
    }
    float acc[2][4][4];
    #pragma unroll
    for (int mt=0;mt<2;mt++)
      #pragma unroll
      for (int nt=0;nt<4;nt++)
        #pragma unroll
        for (int q=0;q<4;q++) acc[mt][nt][q] = 0.f;
    for (int kc = 0; kc < 2; ++kc) {
      __syncthreads();
      #pragma unroll
      for (int it = 0; it < 16; ++it) {
        int f = it*256 + tid;
        int k8 = f >> 8, rem = f & 255;
        Bp4[f] = Wc4[((long long)(kc*16 + k8)*8)*32 + rem];
      }
      __syncthreads();
      #pragma unroll
      for (int k8 = 0; k8 < 16; ++k8) {
        uint32_t a[2][4];
        #pragma unroll
        for (int mt=0;mt<2;mt++) {
          const float* ap = As + (wm*32 + mt*16 + g)*260 + kc*128 + k8*8 + t4;
          a[mt][0] = __float_as_uint(ap[0]);
          a[mt][1] = __float_as_uint(ap[8*260]);
          a[mt][2] = __float_as_uint(ap[4]);
          a[mt][3] = __float_as_uint(ap[8*260+4]);
        }
        float4 b40 = Bp4[(k8*8 + wn*2    )*32 + lane];
        float4 b41 = Bp4[(k8*8 + wn*2 + 1)*32 + lane];
        uint32_t bb[4][2];
        bb[0][0]=__float_as_uint(b40.x); bb[0][1]=__float_as_uint(b40.y);
        bb[1][0]=__float_as_uint(b40.z); bb[1][1]=__float_as_uint(b40.w);
        bb[2][0]=__float_as_uint(b41.x); bb[2][1]=__float_as_uint(b41.y);
        bb[3][0]=__float_as_uint(b41.z); bb[3][1]=__float_as_uint(b41.w);
        #pragma unroll
        for (int mt=0;mt<2;mt++)
          #pragma unroll
          for (int nt=0;nt<4;nt++)
            mma8(acc[mt][nt], a[mt], bb[nt]);
      }
    }
    __syncthreads();
    float* a1s = Bp;
    #pragma unroll
    for (int mt=0;mt<2;mt++) {
      int row0 = wm*32 + mt*16 + g;
      #pragma unroll
      for (int nt=0;nt<4;nt++) {
        int col = wn*32 + nt*8 + 2*t4;
        #pragma unroll
        for (int h=0; h<2; ++h) {
          int row = row0 + 8*h;
          long long rowg = m0 + row;
          const float* np = nterm + (long long)(rowg / T)*128;
          a1s[row*132 + col]     = tf32r(fmaxf(acc[mt][nt][2*h+0] + np[col],   0.f));
          a1s[row*132 + col + 1] = tf32r(fmaxf(acc[mt][nt][2*h+1] + np[col+1], 0.f));
        }
      }
    }
    __syncthreads();
    {
      float acc2[4][4];
      #pragma unroll
      for (int nt=0;nt<4;nt++)
        #pragma unroll
        for (int q=0;q<4;q++) acc2[nt][q] = 0.f;
      const float4* W2p4 = (const float4*)W2s;
      #pragma unroll
      for (int k8 = 0; k8 < 16; ++k8) {
        uint32_t a[4];
        const float* ap = a1s + (wm3*16 + g)*132 + k8*8 + t4;
        a[0] = __float_as_uint(ap[0]);
        a[1] = __float_as_uint(ap[8*132]);
        a[2] = __float_as_uint(ap[4]);
        a[3] = __float_as_uint(ap[8*132+4]);
        float4 b40 = W2p4[(k8*4 + wn3*2    )*32 + lane];
        float4 b41 = W2p4[(k8*4 + wn3*2 + 1)*32 + lane];
        uint32_t bb[4][2];
        bb[0][0]=__float_as_uint(b40.x); bb[0][1]=__float_as_uint(b40.y);
        bb[1][0]=__float_as_uint(b40.z); bb[1][1]=__float_as_uint(b40.w);
        bb[2][0]=__float_as_uint(b41.x); bb[2][1]=__float_as_uint(b41.y);
        bb[3][0]=__float_as_uint(b41.z); bb[3][1]=__float_as_uint(b41.w);
        #pragma unroll
        for (int nt=0;nt<4;nt++)
          mma8(acc2[nt], a, bb[nt]);
      }
      #pragma unroll
      for (int nt=0;nt<4;nt++) {
        int col = wn3*32 + nt*8 + 2*t4;
        float bc0 = b2[col], bc1 = b2[col+1];
        #pragma unroll
        for (int h=0; h<2; ++h) {
          int row = wm3*16 + g + 8*h;
          a2s[row*68 + col]     = fmaxf(acc2[nt][2*h+0] + bc0, 0.f);
          a2s[row*68 + col + 1] = fmaxf(acc2[nt][2*h+1] + bc1, 0.f);
        }
      }
    }
    __syncthreads();
    if (tid < 64) {
      float accv = b3v;
      #pragma unroll 8
      for (int cc=0; cc<64; ++cc) accv = fmaf(a2s[tid*68 + cc], W3s[cc], accv);
      g_ats[m0 + tid] = sigf(accv);
    }
  }
}

// ------------------------------ head ------------------------------
__global__ void head_kernel(const float* __restrict__ inputs,
                            const float* __restrict__ gamma, const float* __restrict__ beta,
                            const float* __restrict__ mean,  const float* __restrict__ var,
                            const float* __restrict__ W1, const float* __restrict__ bb1,
                            const float* __restrict__ W2, const float* __restrict__ bb2,
                            const float* __restrict__ fW, const float* __restrict__ fb,
                            float* __restrict__ out) {
  extern __shared__ float sm[];
  float* xs  = sm;          // 32*256
  float* y1s = xs + 8192;   // 32*256
  float* y2s = y1s + 8192;  // 32*128
  const int tid = threadIdx.x;   // 256
  const int b0 = blockIdx.x * 32;
  for (int r = 0; r < 32; ++r) {
    int k = tid;
    int bb = b0 + r;
    float v = (k < 128) ? g_hfin[bb*128 + k]
                        : inputs[((long long)bb*(T+1) + T)*128 + (k - 128)];
    float nv = (v - mean[k]) * rsqrtf(var[k] + BN_EPS) * gamma[k] + beta[k];
    xs[r*256 + k] = nv;
  }
  __syncthreads();
  {
    float acc[32];
    #pragma unroll
    for (int r=0;r<32;r++) acc[r] = bb1[tid];
    for (int k=0;k<256;++k) {
      float w = W1[k*256 + tid];
      #pragma unroll
      for (int r=0;r<32;r++) acc[r] = fmaf(xs[r*256+k], w, acc[r]);
    }
    #pragma unroll
    for (int r=0;r<32;r++) {
      float v = acc[r];
      y1s[r*256 + tid] = v >= 0.f ? v : LEAKY*v;
    }
  }
  __syncthreads();
  if (tid < 128) {
    float acc[32];
    #pragma unroll
    for (int r=0;r<32;r++) acc[r] = bb2[tid];
    for (int k=0;k<256;++k) {
      float w = W2[k*128 + tid];
      #pragma unroll
      for (int r=0;r<32;r++) acc[r] = fmaf(y1s[r*256+k], w, acc[r]);
    }
    #pragma unroll
    for (int r=0;r<32;r++) {
      float v = acc[r];
      y2s[r*128 + tid] = v >= 0.f ? v : LEAKY*v;
    }
  }
  __syncthreads();
  if (tid < 32) {
    float acc = fb[0];
    for (int k=0;k<128;++k) acc = fmaf(y2s[tid*128+k], fW[k], acc);
    out[b0 + tid] = sigf(acc);
  }
}

// ------------------------------ launch ------------------------------
extern "C" void kernel_launch(void* const* d_in, const int* in_sizes, int n_in,
                              void* d_out, int out_size) {
  (void)in_sizes; (void)n_in; (void)out_size;
  const float* inputs  = (const float*)d_in[0];
  const float* gru_W   = (const float*)d_in[1];
  const float* gru_U   = (const float*)d_in[2];
  const float* gru_b   = (const float*)d_in[3];
  const float* att_W1  = (const float*)d_in[4];
  const float* att_b1  = (const float*)d_in[5];
  const float* att_W2  = (const float*)d_in[6];
  const float* att_b2  = (const float*)d_in[7];
  const float* att_W3  = (const float*)d_in[8];
  const float* att_b3  = (const float*)d_in[9];
  const float* au_Wu   = (const float*)d_in[10];
  const float* au_bu   = (const float*)d_in[11];
  const float* au_Uu   = (const float*)d_in[12];
  const float* au_Wr   = (const float*)d_in[13];
  const float* au_br   = (const float*)d_in[14];
  const float* au_Ur   = (const float*)d_in[15];
  const float* au_Wc   = (const float*)d_in[16];
  const float* au_bc   = (const float*)d_in[17];
  const float* au_Uc   = (const float*)d_in[18];
  const float* bn_gamma= (const float*)d_in[19];
  const float* bn_beta = (const float*)d_in[20];
  const float* bn_mean = (const float*)d_in[21];
  const float* bn_var  = (const float*)d_in[22];
  const float* d_W1    = (const float*)d_in[23];
  const float* d_b1    = (const float*)d_in[24];
  const float* d_W2    = (const float*)d_in[25];
  const float* d_b2    = (const float*)d_in[26];
  const float* f_W     = (const float*)d_in[27];
  const float* f_b     = (const float*)d_in[28];
  float* out = (float*)d_out;

  const size_t sm_gemm = (64*132 + 16384)*sizeof(float);      // 99328
  const size_t sm_scan = 98304 + 2*A_BUF*sizeof(__nv_bfloat16); // 98304+17408 = 115712
  const size_t sm_attf = (16640 + 16384 + 8192 + 4352 + 64)*sizeof(float); // 182528
  const size_t sm_head = (8192*2 + 4096)*sizeof(float);
  cudaFuncSetAttribute(gemm_v2,        cudaFuncAttributeMaxDynamicSharedMemorySize, (int)sm_gemm);
  cudaFuncSetAttribute(gru_scan_mma,   cudaFuncAttributeMaxDynamicSharedMemorySize, (int)sm_scan);
  cudaFuncSetAttribute(augru_scan_mma, cudaFuncAttributeMaxDynamicSharedMemorySize, (int)sm_scan);
  cudaFuncSetAttribute(att_fused,      cudaFuncAttributeMaxDynamicSharedMemorySize, (int)sm_attf);
  cudaFuncSetAttribute(head_kernel,    cudaFuncAttributeMaxDynamicSharedMemorySize, (int)sm_head);

  float *p_Xp, *p_hs, *p_X3, *p_newsterm, *p_bau;
  float *p_WpgW, *p_Wpau, *p_Wp1bc, *p_Wpcat, *p_Wpatt2;
  uint32_t *p_Ubg, *p_Uba;
  cudaGetSymbolAddress((void**)&p_Xp,       g_Xp);
  cudaGetSymbolAddress((void**)&p_hs,       g_hs);
  cudaGetSymbolAddress((void**)&p_X3,       g_X3);
  cudaGetSymbolAddress((void**)&p_newsterm, g_newsterm);
  cudaGetSymbolAddress((void**)&p_bau,      g_bau);
  cudaGetSymbolAddress((void**)&p_Ubg,      g_Ubf_gru);
  cudaGetSymbolAddress((void**)&p_Uba,      g_Ubf_au);
  cudaGetSymbolAddress((void**)&p_WpgW,     g_Wp_gruW);
  cudaGetSymbolAddress((void**)&p_Wpau,     g_Wp_au);
  cudaGetSymbolAddress((void**)&p_Wp1bc,    g_Wp_1bc);
  cudaGetSymbolAddress((void**)&p_Wpcat,    g_Wp_cat);
  cudaGetSymbolAddress((void**)&p_Wpatt2,   g_Wp_att2);

  cudaStream_t s2;
  cudaStreamCreateWithFlags(&s2, cudaStreamNonBlocking);
  cudaEvent_t evFork, evJoin;
  cudaEventCreateWithFlags(&evFork, cudaEventDisableTiming);
  cudaEventCreateWithFlags(&evJoin, cudaEventDisableTiming);

  // 1) fold weights, then all fragment packs
  prep_kernel<<<192, 256>>>(au_Wu, au_bu, au_Wr, au_br, au_Wc, au_bc,
                            au_Uu, au_Ur, au_Uc, att_W1);
  pack_all<<<800, 256>>>(gru_U, gru_W, att_W2);
  // 2) Xp = hist @ gru_W + gru_b[0]
  gemm_v2<<<dim3(BT/64, 3), 256, sm_gemm>>>(inputs, T, (long long)(T+1)*128, 128,
                                            p_WpgW, 24, gru_b, p_Xp, 384);
  // 3) newsterm = news @ (W1B+W1C) + b1
  gemm_v2<<<dim3(B/64, 1), 256, sm_gemm>>>(inputs + (long long)T*128, 1, (long long)(T+1)*128, 128,
                                           p_Wp1bc, 8, att_b1, p_newsterm, 128);
  // 4) GRU recurrence -> hs (bf16 tensor-core scan)
  gru_scan_mma<<<B/32, 256, sm_scan>>>(p_Xp, p_Ubg, gru_b + 384, p_hs);
  // fork: X3 gemm on s2, attention on main stream
  cudaEventRecord(evFork, 0);
  cudaStreamWaitEvent(s2, evFork, 0);
  // 5) fused attention -> g_ats
  att_fused<<<148, 256, sm_attf>>>(p_hs, inputs, p_Wpcat, p_Wpatt2,
                                   att_b2, att_W3, att_b3, p_newsterm);
  // 6) X3 = hs @ [Wu|Wr|Wc] + [bu|br|bc]   (side stream)
  gemm_v2<<<dim3(BT/64, 3), 256, sm_gemm, s2>>>(p_hs, 1<<30, 0LL, 128,
                                                p_Wpau, 24, p_bau, p_X3, 384);
  cudaEventRecord(evJoin, s2);
  cudaStreamWaitEvent(0, evJoin, 0);
  // 7) AUGRU recurrence -> hfin (bf16 tensor-core scan)
  augru_scan_mma<<<B/32, 256, sm_scan>>>(p_X3, p_Uba);
  // 8) BN + dense head -> out
  head_kernel<<<B/32, 256, sm_head>>>(inputs, bn_gamma, bn_beta, bn_mean, bn_var,
                                      d_W1, d_b1, d_W2, d_b2, f_W, f_b, out);
}